// round 1
// baseline (speedup 1.0000x reference)
#include <cuda_runtime.h>
#include <math.h>

#define Bq   128
#define Tq   512
#define Iq   512
#define Hq   1024
#define G4q  4096
#define TGTq 512

typedef unsigned long long ull;

// Persistent scratch (no cudaMalloc allowed). h double-buffered, c single.
__device__ float g_h[2][Hq * Bq];
__device__ float g_c[Hq * Bq];

// ---------------------------------------------------------------------------
// Packed fp32x2 helpers (Blackwell: FFMA2 doubles fp32 FMA throughput)
// ---------------------------------------------------------------------------
__device__ __forceinline__ void ffma2(ull &acc, ull a, ull b) {
    asm("fma.rn.f32x2 %0, %1, %2, %0;" : "+l"(acc) : "l"(a), "l"(b));
}
__device__ __forceinline__ ull dup2(float x) {
    ull r; asm("mov.b64 %0, {%1, %1};" : "=l"(r) : "f"(x)); return r;
}
__device__ __forceinline__ void unpk(ull v, float &lo, float &hi) {
    asm("mov.b64 {%0, %1}, %2;" : "=f"(lo), "=f"(hi) : "l"(v));
}
__device__ __forceinline__ float sigf(float x) { return 1.0f / (1.0f + expf(-x)); }

// ---------------------------------------------------------------------------
// Zero h[0] and c at the start of every replay (graph determinism).
// ---------------------------------------------------------------------------
__global__ void k_init() {
    int n = Hq * Bq;
    for (int i = blockIdx.x * blockDim.x + threadIdx.x; i < n;
         i += gridDim.x * blockDim.x) {
        g_h[0][i] = 0.0f;
        g_c[i]    = 0.0f;
    }
}

// ---------------------------------------------------------------------------
// One LSTM step (reversed time: step s uses XW[:, T-1-s, :]).
// Grid: 128 CTAs x 256 threads. CTA c owns hidden units [c*8, c*8+8):
//   32 gate rows (8 per gate i/f/g/o) x 128 batch, K = 1024 (h) + 512 (x).
// Gates[row][b] = sum_k W'[row][k] * v[k][b], v = [h ; x_t], W' = [W_hh W_ih].
// Then the cell update on this CTA's private c slice; new h -> other buffer.
// ---------------------------------------------------------------------------
__global__ __launch_bounds__(256) void k_step(
    const float* __restrict__ XW,
    const float* __restrict__ Wih,
    const float* __restrict__ Whh,
    const float* __restrict__ bih,
    const float* __restrict__ bhh,
    int s)
{
    __shared__ float Ws[32][36];    // [k within chunk][local row], padded
    __shared__ float Hs[32][132];   // [k within chunk][batch], padded
    __shared__ float Gs[4][8][128]; // [gate][unit][batch]

    const int tid = threadIdx.x;
    const int c   = blockIdx.x;
    const int t   = Tq - 1 - s;
    const float* __restrict__ h_in = g_h[s & 1];
    float* __restrict__ h_out      = g_h[(s + 1) & 1];

    // compute-phase mapping: warp-uniform rg, lanes sweep pg
    const int rg = tid >> 6;   // 0..3 -> rows rg*8..rg*8+7 (== gate rg)
    const int pg = tid & 63;   // batch columns pg and pg+64

    // staging mapping for W tile (32 rows x 32 k): 1 float4 per thread
    const int w_row  = tid >> 3;  // 0..31 local row
    const int w_kq   = tid & 7;   // 0..7 float4 slot in k
    const int grow_w = ((w_row >> 3) * Hq) + c * 8 + (w_row & 7); // global W row

    ull acc[4][2];
#pragma unroll
    for (int p = 0; p < 4; p++)
#pragma unroll
        for (int j = 0; j < 2; j++) acc[p][j] = 0ull;

    float4 pw;      // prefetched W fragment
    float4 ph[4];   // prefetched h/x fragments

    // prefetch chunk 0 (h-phase)
    pw = *(const float4*)&Whh[(size_t)grow_w * Hq + w_kq * 4];
#pragma unroll
    for (int i2 = 0; i2 < 4; i2++) {
        int f = tid + i2 * 256;
        int row = f >> 5, bq = f & 31;
        ph[i2] = *(const float4*)&h_in[row * Bq + bq * 4];
    }

    const int NCH = 48; // 32 chunks of h (K=1024) + 16 chunks of x (K=512)
    for (int ch = 0; ch < NCH; ch++) {
        // ---- store staged fragments to SMEM ----
        Ws[w_kq * 4 + 0][w_row] = pw.x;
        Ws[w_kq * 4 + 1][w_row] = pw.y;
        Ws[w_kq * 4 + 2][w_row] = pw.z;
        Ws[w_kq * 4 + 3][w_row] = pw.w;
        if (ch < 32) {
#pragma unroll
            for (int i2 = 0; i2 < 4; i2++) {
                int f = tid + i2 * 256;
                int row = f >> 5, bq = f & 31;
                *(float4*)&Hs[row][bq * 4] = ph[i2];
            }
        } else {
#pragma unroll
            for (int i2 = 0; i2 < 4; i2++) {
                int f = tid + i2 * 256;
                int b = f >> 3, kq = f & 7;
                Hs[kq * 4 + 0][b] = ph[i2].x;
                Hs[kq * 4 + 1][b] = ph[i2].y;
                Hs[kq * 4 + 2][b] = ph[i2].z;
                Hs[kq * 4 + 3][b] = ph[i2].w;
            }
        }
        __syncthreads();

        // ---- prefetch next chunk ----
        int nc = ch + 1;
        if (nc < NCH) {
            if (nc < 32) {
                int k0 = nc * 32;
                pw = *(const float4*)&Whh[(size_t)grow_w * Hq + k0 + w_kq * 4];
#pragma unroll
                for (int i2 = 0; i2 < 4; i2++) {
                    int f = tid + i2 * 256;
                    int row = f >> 5, bq = f & 31;
                    ph[i2] = *(const float4*)&h_in[(k0 + row) * Bq + bq * 4];
                }
            } else {
                int k0 = (nc - 32) * 32;
                pw = *(const float4*)&Wih[(size_t)grow_w * Iq + k0 + w_kq * 4];
#pragma unroll
                for (int i2 = 0; i2 < 4; i2++) {
                    int f = tid + i2 * 256;
                    int b = f >> 3, kq = f & 7;
                    ph[i2] = *(const float4*)&XW[((size_t)b * Tq + t) * Iq + k0 + kq * 4];
                }
            }
        }

        // ---- compute: 32 K-steps, packed fp32x2 over row pairs ----
#pragma unroll
        for (int k = 0; k < 32; k++) {
            const ull* wp = (const ull*)&Ws[k][rg * 8];
            ull w0 = wp[0], w1 = wp[1], w2 = wp[2], w3 = wp[3];
            ull h0 = dup2(Hs[k][pg]);
            ull h1 = dup2(Hs[k][pg + 64]);
            ffma2(acc[0][0], w0, h0);
            ffma2(acc[1][0], w1, h0);
            ffma2(acc[2][0], w2, h0);
            ffma2(acc[3][0], w3, h0);
            ffma2(acc[0][1], w0, h1);
            ffma2(acc[1][1], w1, h1);
            ffma2(acc[2][1], w2, h1);
            ffma2(acc[3][1], w3, h1);
        }
        __syncthreads();
    }

    // ---- gate exchange via SMEM ----
#pragma unroll
    for (int p = 0; p < 4; p++) {
#pragma unroll
        for (int j = 0; j < 2; j++) {
            float lo, hi;
            unpk(acc[p][j], lo, hi);
            Gs[rg][2 * p + 0][pg + 64 * j] = lo;
            Gs[rg][2 * p + 1][pg + 64 * j] = hi;
        }
    }
    __syncthreads();

    // ---- cell update: thread -> (unit u, 4 batches) ----
    {
        int u  = tid >> 5;          // 0..7
        int bb = (tid & 31) * 4;    // batch base
        int gbase = c * 8 + u;      // global hidden unit

        float bi = bih[0 * Hq + gbase] + bhh[0 * Hq + gbase];
        float bf = bih[1 * Hq + gbase] + bhh[1 * Hq + gbase];
        float bg = bih[2 * Hq + gbase] + bhh[2 * Hq + gbase];
        float bo = bih[3 * Hq + gbase] + bhh[3 * Hq + gbase];

        float4 iv = *(const float4*)&Gs[0][u][bb];
        float4 fv = *(const float4*)&Gs[1][u][bb];
        float4 gv = *(const float4*)&Gs[2][u][bb];
        float4 ov = *(const float4*)&Gs[3][u][bb];

        size_t cidx = (size_t)gbase * Bq + bb;
        float4 cold = *(const float4*)&g_c[cidx];

        float4 cn, hn;
        {
            float ig, fg, gg, og;
            ig = sigf(iv.x + bi); fg = sigf(fv.x + bf); gg = tanhf(gv.x + bg); og = sigf(ov.x + bo);
            cn.x = fg * cold.x + ig * gg; hn.x = og * tanhf(cn.x);
            ig = sigf(iv.y + bi); fg = sigf(fv.y + bf); gg = tanhf(gv.y + bg); og = sigf(ov.y + bo);
            cn.y = fg * cold.y + ig * gg; hn.y = og * tanhf(cn.y);
            ig = sigf(iv.z + bi); fg = sigf(fv.z + bf); gg = tanhf(gv.z + bg); og = sigf(ov.z + bo);
            cn.z = fg * cold.z + ig * gg; hn.z = og * tanhf(cn.z);
            ig = sigf(iv.w + bi); fg = sigf(fv.w + bf); gg = tanhf(gv.w + bg); og = sigf(ov.w + bo);
            cn.w = fg * cold.w + ig * gg; hn.w = og * tanhf(cn.w);
        }
        *(float4*)&g_c[cidx]  = cn;
        *(float4*)&h_out[cidx] = hn;
    }
}

// ---------------------------------------------------------------------------
// Final linear: out[b][tgt] = b_lin[tgt] + sum_k h[k][b] * W_lin[tgt][k]
// Final h lives in g_h[0] (512 steps: last write -> buffer (511+1)&1 = 0).
// ---------------------------------------------------------------------------
__global__ __launch_bounds__(256) void k_lin(
    const float* __restrict__ Wlin,
    const float* __restrict__ blin,
    float* __restrict__ out)
{
    int gid = blockIdx.x * blockDim.x + threadIdx.x; // 65536 threads
    int b   = gid & (Bq - 1);
    int tgt = gid >> 7;
    const float* __restrict__ h = g_h[0];

    float acc = blin[tgt];
    const float* __restrict__ wrow = Wlin + (size_t)tgt * Hq;
#pragma unroll 8
    for (int k = 0; k < Hq; k++) {
        acc += h[k * Bq + b] * wrow[k];
    }
    out[(size_t)b * TGTq + tgt] = acc;
}

// ---------------------------------------------------------------------------
extern "C" void kernel_launch(void* const* d_in, const int* in_sizes, int n_in,
                              void* d_out, int out_size)
{
    const float* XW   = (const float*)d_in[0];
    const float* Wih  = (const float*)d_in[1];
    const float* Whh  = (const float*)d_in[2];
    const float* bih  = (const float*)d_in[3];
    const float* bhh  = (const float*)d_in[4];
    const float* Wlin = (const float*)d_in[5];
    const float* blin = (const float*)d_in[6];
    float* out = (float*)d_out;

    k_init<<<128, 256>>>();
    for (int s = 0; s < Tq; s++) {
        k_step<<<128, 256>>>(XW, Wih, Whh, bih, bhh, s);
    }
    k_lin<<<(Bq * TGTq) / 256, 256>>>(Wlin, blin, out);
}

// round 5
// speedup vs baseline: 2.2442x; 2.2442x over previous
#include <cuda_runtime.h>
#include <cuda_bf16.h>
#include <math.h>
#include <stdint.h>

typedef __nv_bfloat16 bf16;

#define Bq   128
#define Tq   512
#define Iq   512
#define Hq   1024
#define G4   4096
#define TGTq 512
#define NB   65536   // Tq * Bq
#define NCTA 128

// ---------------- persistent-kernel SMEM layout --------------------------
#define PA          1032                   // A row pitch (halves): 1024 + 8 pad
#define A_SPL_B     (32 * PA * 2)          // 66048 B per split
#define BBASE       (2 * A_SPL_B)          // 132096
#define BSPL        18432                  // 128 rows x 72 halves x 2B
#define BBUF_B      (2 * BSPL)             // hi+lo per buffer
#define SMEM_PERS   (BBASE + 2 * BBUF_B)   // 205824 B

// ---------------- xproj GEMM SMEM layout (R4 style) ----------------------
#define SP          72
#define REG_BYTES   (128 * SP * 2)
#define XBUF_BYTES  (4 * REG_BYTES)
#define SMEM_XP     (2 * XBUF_BYTES)       // 147456 B

// ---------------------------------------------------------------------------
// Persistent device scratch (no cudaMalloc allowed)
// ---------------------------------------------------------------------------
__device__ __align__(16) bf16 g_Whh_hi[(size_t)G4 * Hq];
__device__ __align__(16) bf16 g_Whh_lo[(size_t)G4 * Hq];
__device__ __align__(16) bf16 g_Wih_hi[(size_t)G4 * Iq];
__device__ __align__(16) bf16 g_Wih_lo[(size_t)G4 * Iq];
__device__ __align__(16) bf16 g_x_hi[(size_t)NB * Iq];   // [t*128+b][i]
__device__ __align__(16) bf16 g_x_lo[(size_t)NB * Iq];
__device__ __align__(16) bf16 g_h_hi[2][Bq * Hq];        // [buf][b][k]
__device__ __align__(16) bf16 g_h_lo[2][Bq * Hq];
__device__ float g_hf[Hq * Bq];                          // [u][b] final h
__device__ float g_xp[(size_t)G4 * NB];                  // x-proj [row][t*128+b]
__device__ unsigned g_bar_count = 0;
__device__ unsigned g_bar_gen   = 0;

// ---------------------------------------------------------------------------
// PTX helpers (plain sm_100 feature set)
// ---------------------------------------------------------------------------
__device__ __forceinline__ uint32_t smem_u32(const void* p) {
    uint32_t a;
    asm("{ .reg .u64 t; cvta.to.shared.u64 t, %1; cvt.u32.u64 %0, t; }"
        : "=r"(a) : "l"(p));
    return a;
}
__device__ __forceinline__ void ldsm4(uint32_t* r, uint32_t addr) {
    asm volatile("ldmatrix.sync.aligned.m8n8.x4.shared.b16 {%0,%1,%2,%3}, [%4];"
                 : "=r"(r[0]), "=r"(r[1]), "=r"(r[2]), "=r"(r[3]) : "r"(addr));
}
__device__ __forceinline__ void ldsm2(uint32_t* r, uint32_t addr) {
    asm volatile("ldmatrix.sync.aligned.m8n8.x2.shared.b16 {%0,%1}, [%2];"
                 : "=r"(r[0]), "=r"(r[1]) : "r"(addr));
}
__device__ __forceinline__ void mma16816(float* c, const uint32_t* a, const uint32_t* b) {
    asm volatile(
        "mma.sync.aligned.m16n8k16.row.col.f32.bf16.bf16.f32 "
        "{%0,%1,%2,%3}, {%4,%5,%6,%7}, {%8,%9}, {%0,%1,%2,%3};"
        : "+f"(c[0]), "+f"(c[1]), "+f"(c[2]), "+f"(c[3])
        : "r"(a[0]), "r"(a[1]), "r"(a[2]), "r"(a[3]), "r"(b[0]), "r"(b[1]));
}
#define CP16(d, s) \
    asm volatile("cp.async.cg.shared.global [%0], [%1], 16;" :: "r"(d), "l"(s) : "memory")
#define CPCOMMIT() asm volatile("cp.async.commit_group;" ::: "memory")

__device__ __forceinline__ float sigf(float x) { return 1.0f / (1.0f + expf(-x)); }

// sense-reversing grid barrier (all NCTA CTAs co-resident)
__device__ __forceinline__ void gbar() {
    __syncthreads();
    if (threadIdx.x == 0) {
        unsigned gen;
        asm volatile("ld.acquire.gpu.global.u32 %0, [%1];"
                     : "=r"(gen) : "l"(&g_bar_gen) : "memory");
        __threadfence();
        if (atomicAdd(&g_bar_count, 1u) == NCTA - 1) {
            g_bar_count = 0;
            __threadfence();
            asm volatile("st.release.gpu.global.u32 [%0], %1;"
                         :: "l"(&g_bar_gen), "r"(gen + 1) : "memory");
        } else {
            unsigned cur;
            do {
                asm volatile("nanosleep.u32 64;");
                asm volatile("ld.acquire.gpu.global.u32 %0, [%1];"
                             : "=r"(cur) : "l"(&g_bar_gen) : "memory");
            } while (cur == gen);
        }
    }
    __syncthreads();
}

// ---------------------------------------------------------------------------
// Prep kernels
// ---------------------------------------------------------------------------
__global__ void k_prep_w(const float* __restrict__ Wih, const float* __restrict__ Whh) {
    int r = blockIdx.x;
    for (int k = threadIdx.x; k < Hq; k += 256) {
        float w = Whh[(size_t)r * Hq + k];
        bf16 hi = __float2bfloat16(w);
        g_Whh_hi[(size_t)r * Hq + k] = hi;
        g_Whh_lo[(size_t)r * Hq + k] = __float2bfloat16(w - __bfloat162float(hi));
    }
    for (int k = threadIdx.x; k < Iq; k += 256) {
        float w = Wih[(size_t)r * Iq + k];
        bf16 hi = __float2bfloat16(w);
        g_Wih_hi[(size_t)r * Iq + k] = hi;
        g_Wih_lo[(size_t)r * Iq + k] = __float2bfloat16(w - __bfloat162float(hi));
    }
}

__global__ void k_prep_x(const float* __restrict__ XW) {
    int bx = blockIdx.x;          // t*128 + b
    int t = bx >> 7, b = bx & 127;
    const float* __restrict__ src = XW + ((size_t)b * Tq + t) * Iq;
    size_t doff = (size_t)bx * Iq;
    for (int i = threadIdx.x; i < Iq; i += 256) {
        float v = src[i];
        bf16 hi = __float2bfloat16(v);
        g_x_hi[doff + i] = hi;
        g_x_lo[doff + i] = __float2bfloat16(v - __bfloat162float(hi));
    }
}

__global__ void k_init() {
    int n = Bq * Hq;
    for (int i = blockIdx.x * blockDim.x + threadIdx.x; i < n;
         i += gridDim.x * blockDim.x) {
        bf16 z = __float2bfloat16(0.0f);
        g_h_hi[0][i] = z; g_h_lo[0][i] = z;
        g_h_hi[1][i] = z; g_h_lo[1][i] = z;
    }
}

// ---------------------------------------------------------------------------
// x-projection GEMM (bf16 3-term split, mma.sync): g_xp = Wih * x^T
// grid (32, 512): C tile 128(M rows of 4096) x 128(N cols of 65536), K=512.
// ---------------------------------------------------------------------------
__global__ __launch_bounds__(256) void k_xproj() {
    extern __shared__ __align__(128) uint8_t smem[];
    const uint32_t sb = smem_u32(smem);
    const int tid = threadIdx.x;
    const int L = tid & 31, w = tid >> 5;
    const int mw = w & 3, nw = w >> 2;   // warp tile M32 x N64

    const int mrow0 = blockIdx.x * 128;
    const int nrow0 = blockIdx.y * 128;
    const int lsc = tid & 7;

    const uint32_t a_off = ((mw * 32 + (L & 15)) * SP + (L >> 4) * 8) * 2;
    const uint32_t b_off = ((nw * 64 + (L & 7)) * SP + ((L >> 3) & 1) * 8) * 2;

    float acc[2][8][4];
#pragma unroll
    for (int mi = 0; mi < 2; mi++)
#pragma unroll
        for (int nj = 0; nj < 8; nj++)
#pragma unroll
            for (int q = 0; q < 4; q++) acc[mi][nj][q] = 0.0f;

    auto load_chunk = [&](int buf, int ch) {
        const int gk = ch * 64 + lsc * 8;
        const uint32_t dstbase = sb + buf * XBUF_BYTES;
#pragma unroll
        for (int i = 0; i < 4; i++) {
            int row = (tid >> 3) + i * 32;
            uint32_t doff = (uint32_t)row * 144 + lsc * 16;
            size_t ao = (size_t)(mrow0 + row) * Iq + gk;
            size_t bo = (size_t)(nrow0 + row) * Iq + gk;
            CP16(dstbase + 0 * REG_BYTES + doff, g_Wih_hi + ao);
            CP16(dstbase + 1 * REG_BYTES + doff, g_Wih_lo + ao);
            CP16(dstbase + 2 * REG_BYTES + doff, g_x_hi + bo);
            CP16(dstbase + 3 * REG_BYTES + doff, g_x_lo + bo);
        }
        CPCOMMIT();
    };

    load_chunk(0, 0);
    load_chunk(1, 1);
    for (int c = 0; c < 8; c++) {
        if (c < 7) asm volatile("cp.async.wait_group 1;" ::: "memory");
        else       asm volatile("cp.async.wait_group 0;" ::: "memory");
        __syncthreads();
        const uint32_t base = sb + (c & 1) * XBUF_BYTES;
#pragma unroll
        for (int ki = 0; ki < 4; ki++) {
            uint32_t ah[2][4], al[2][4], bh[8][2], bl[8][2];
#pragma unroll
            for (int mi = 0; mi < 2; mi++) {
                uint32_t ad = base + a_off + (mi * 16 * SP + ki * 16) * 2;
                ldsm4(ah[mi], ad);
                ldsm4(al[mi], ad + REG_BYTES);
            }
#pragma unroll
            for (int nj = 0; nj < 8; nj++) {
                uint32_t bd = base + 2 * REG_BYTES + b_off + (nj * 8 * SP + ki * 16) * 2;
                ldsm2(bh[nj], bd);
                ldsm2(bl[nj], bd + REG_BYTES);
            }
#pragma unroll
            for (int mi = 0; mi < 2; mi++)
#pragma unroll
                for (int nj = 0; nj < 8; nj++) {
                    mma16816(acc[mi][nj], ah[mi], bh[nj]);
                    mma16816(acc[mi][nj], ah[mi], bl[nj]);
                    mma16816(acc[mi][nj], al[mi], bh[nj]);
                }
        }
        if (c + 2 < 8) {
            __syncthreads();
            load_chunk(c & 1, c + 2);
        }
    }

#pragma unroll
    for (int mi = 0; mi < 2; mi++)
#pragma unroll
        for (int nj = 0; nj < 8; nj++) {
            int row = mrow0 + mw * 32 + mi * 16 + (L >> 2);
            int col = nrow0 + nw * 64 + nj * 8 + (L & 3) * 2;
            float* p = g_xp + (size_t)row * NB + col;
            *(float2*)p            = make_float2(acc[mi][nj][0], acc[mi][nj][1]);
            *(float2*)(p + 8 * NB) = make_float2(acc[mi][nj][2], acc[mi][nj][3]);
        }
}

// ---------------------------------------------------------------------------
// Persistent recurrence: 128 CTAs x 256 threads, all 512 steps in one launch.
// CTA c owns hidden units u = c*8 .. c*8+7 (32 gate rows: row32 = g*8+j).
// A (Whh splits, 32 rows x K=1024) resident in SMEM. B (h) streamed per step.
// Warp tile: M32 x N16 (8 warps cover N=128). Cell state in registers.
// ---------------------------------------------------------------------------
__global__ __launch_bounds__(256, 1) void k_recur(const float* __restrict__ bih,
                                                  const float* __restrict__ bhh) {
    extern __shared__ __align__(128) uint8_t smem[];
    const uint32_t sb = smem_u32(smem);
    const int tid = threadIdx.x;
    const int c = blockIdx.x;
    const int L = tid & 31;
    const int nw = tid >> 5;             // warp = N group of 16 cols

    // ---- load resident A (Whh hi/lo) : 32 rows x 1024 halves each ----
    {
        int row32 = tid >> 3;            // 0..31
        int g = row32 >> 3, j = row32 & 7;
        size_t grow = ((size_t)g * Hq + c * 8 + j) * Hq;
        int seg = tid & 7;
#pragma unroll
        for (int it = 0; it < 16; it++) {
            int s16 = seg + it * 8;      // 0..127 16B segments per row
            uint32_t doff = (uint32_t)row32 * (PA * 2) + s16 * 16;
            CP16(sb + doff,           g_Whh_hi + grow + s16 * 8);
            CP16(sb + A_SPL_B + doff, g_Whh_lo + grow + s16 * 8);
        }
        CPCOMMIT();
    }

    // per-thread cell mapping
    const int j = (L >> 2) & 7;          // unit within CTA
    const int u = c * 8 + j;             // global hidden unit
    const int c0 = nw * 16 + (L & 3) * 2; // batch col base; cols c0,c0+1,c0+8,c0+9
    float bias[4], cc[4];
#pragma unroll
    for (int g = 0; g < 4; g++) {
        bias[g] = bih[g * Hq + u] + bhh[g * Hq + u];
        cc[g] = 0.0f;                    // cc indexed by (nj*2+e), init 0
    }

    // ldmatrix per-lane offsets
    const uint32_t aoff = (((L & 15) * PA + (L >> 4) * 8)) * 2;
    const uint32_t boff = (((L & 7) * 72 + ((L >> 3) & 1) * 8)) * 2 + nw * 16 * 144;

    asm volatile("cp.async.wait_group 0;" ::: "memory");
    __syncthreads();

    for (int s = 0; s < Tq; s++) {
        const int t = Tq - 1 - s;
        const bf16* __restrict__ hin_hi = g_h_hi[s & 1];
        const bf16* __restrict__ hin_lo = g_h_lo[s & 1];
        bf16* __restrict__ hout_hi = g_h_hi[(s + 1) & 1];
        bf16* __restrict__ hout_lo = g_h_lo[(s + 1) & 1];

        // prefetch x-projection values for this thread's 16 gate outputs
        float2 xp[4][2];
#pragma unroll
        for (int g = 0; g < 4; g++)
#pragma unroll
            for (int nj = 0; nj < 2; nj++)
                xp[g][nj] = *(const float2*)&g_xp[(size_t)(g * Hq + u) * NB
                                                 + t * Bq + c0 + nj * 8];

        float acc[2][2][4];
#pragma unroll
        for (int mi = 0; mi < 2; mi++)
#pragma unroll
            for (int nj = 0; nj < 2; nj++)
#pragma unroll
                for (int q = 0; q < 4; q++) acc[mi][nj][q] = 0.0f;

        auto loadB = [&](int buf, int ch) {
            int b = tid >> 1;
            uint32_t dbase = sb + BBASE + buf * BBUF_B + (uint32_t)b * 144;
            size_t srow = (size_t)b * Hq + ch * 64;
#pragma unroll
            for (int q = 0; q < 4; q++) {
                int sg = (tid & 1) * 4 + q;
                CP16(dbase + sg * 16,        hin_hi + srow + sg * 8);
                CP16(dbase + BSPL + sg * 16, hin_lo + srow + sg * 8);
            }
            CPCOMMIT();
        };

        loadB(0, 0);
        loadB(1, 1);
#pragma unroll 4
        for (int ch = 0; ch < 16; ch++) {
            if (ch < 15) asm volatile("cp.async.wait_group 1;" ::: "memory");
            else         asm volatile("cp.async.wait_group 0;" ::: "memory");
            __syncthreads();
            const uint32_t bbase = sb + BBASE + (ch & 1) * BBUF_B + boff;
#pragma unroll
            for (int ki = 0; ki < 4; ki++) {
                const int k = ch * 64 + ki * 16;
                uint32_t ah[2][4], al[2][4], bh[2][2], bl[2][2];
#pragma unroll
                for (int mi = 0; mi < 2; mi++) {
                    uint32_t ad = sb + aoff + (uint32_t)(mi * 16 * PA + k) * 2;
                    ldsm4(ah[mi], ad);
                    ldsm4(al[mi], ad + A_SPL_B);
                }
#pragma unroll
                for (int nj = 0; nj < 2; nj++) {
                    uint32_t bd = bbase + (uint32_t)(nj * 8) * 144 + ki * 32;
                    ldsm2(bh[nj], bd);
                    ldsm2(bl[nj], bd + BSPL);
                }
#pragma unroll
                for (int mi = 0; mi < 2; mi++)
#pragma unroll
                    for (int nj = 0; nj < 2; nj++) {
                        mma16816(acc[mi][nj], ah[mi], bh[nj]);
                        mma16816(acc[mi][nj], ah[mi], bl[nj]);
                        mma16816(acc[mi][nj], al[mi], bh[nj]);
                    }
            }
            __syncthreads();
            if (ch + 2 < 16) loadB(ch & 1, ch + 2);
        }

        // ---- register-local cell update for 4 (batch) positions ----
#pragma unroll
        for (int nj = 0; nj < 2; nj++)
#pragma unroll
            for (int e = 0; e < 2; e++) {
                int b = c0 + nj * 8 + e;
                float xpi = e ? xp[0][nj].y : xp[0][nj].x;
                float xpf = e ? xp[1][nj].y : xp[1][nj].x;
                float xpg = e ? xp[2][nj].y : xp[2][nj].x;
                float xpo = e ? xp[3][nj].y : xp[3][nj].x;
                float ig = sigf(acc[0][nj][e]     + xpi + bias[0]);
                float fg = sigf(acc[0][nj][2 + e] + xpf + bias[1]);
                float gg = tanhf(acc[1][nj][e]    + xpg + bias[2]);
                float og = sigf(acc[1][nj][2 + e] + xpo + bias[3]);
                int ci = nj * 2 + e;
                float cv = fg * cc[ci] + ig * gg;
                cc[ci] = cv;
                float h = og * tanhf(cv);
                bf16 hi = __float2bfloat16(h);
                hout_hi[b * Hq + u] = hi;
                hout_lo[b * Hq + u] = __float2bfloat16(h - __bfloat162float(hi));
                if (s == Tq - 1) g_hf[u * Bq + b] = h;
            }

        gbar();
    }
}

// ---------------------------------------------------------------------------
// Final linear
// ---------------------------------------------------------------------------
__global__ __launch_bounds__(256) void k_lin(const float* __restrict__ Wlin,
                                             const float* __restrict__ blin,
                                             float* __restrict__ out) {
    int gid = blockIdx.x * blockDim.x + threadIdx.x;
    int b = gid & (Bq - 1);
    int tgt = gid >> 7;
    float acc = blin[tgt];
    const float* __restrict__ wrow = Wlin + (size_t)tgt * Hq;
#pragma unroll 8
    for (int k = 0; k < Hq; k++) {
        acc += g_hf[k * Bq + b] * wrow[k];
    }
    out[(size_t)b * TGTq + tgt] = acc;
}

// ---------------------------------------------------------------------------
extern "C" void kernel_launch(void* const* d_in, const int* in_sizes, int n_in,
                              void* d_out, int out_size)
{
    const float* XW   = (const float*)d_in[0];
    const float* Wih  = (const float*)d_in[1];
    const float* Whh  = (const float*)d_in[2];
    const float* bih  = (const float*)d_in[3];
    const float* bhh  = (const float*)d_in[4];
    const float* Wlin = (const float*)d_in[5];
    const float* blin = (const float*)d_in[6];
    float* out = (float*)d_out;

    cudaFuncSetAttribute(k_xproj, cudaFuncAttributeMaxDynamicSharedMemorySize, SMEM_XP);
    cudaFuncSetAttribute(k_recur, cudaFuncAttributeMaxDynamicSharedMemorySize, SMEM_PERS);

    k_prep_w<<<G4, 256>>>(Wih, Whh);
    k_prep_x<<<NB, 256>>>(XW);
    k_init<<<128, 256>>>();
    k_xproj<<<dim3(32, 512, 1), 256, SMEM_XP>>>();
    k_recur<<<NCTA, 256, SMEM_PERS>>>(bih, bhh);
    k_lin<<<(Bq * TGTq) / 256, 256>>>(Wlin, blin, out);
}

// round 7
// speedup vs baseline: 2.2445x; 1.0001x over previous
#include <cuda_runtime.h>
#include <cuda_bf16.h>
#include <math.h>
#include <stdint.h>

typedef __nv_bfloat16 bf16;

#define Bq   128
#define Tq   512
#define Iq   512
#define Hq   1024
#define G4   4096
#define TGTq 512
#define NB   65536   // Tq * Bq
#define NCTA 128

// ---------------- persistent-kernel SMEM layout --------------------------
#define PA          1032                   // A row pitch (halves): 1024 + 8 pad
#define A_SPL_B     (32 * PA * 2)          // 66048 B per split
#define BBASE       (2 * A_SPL_B)          // 132096
#define BSPL        18432                  // 128 rows x 72 halves x 2B
#define BBUF_B      (2 * BSPL)             // hi+lo per buffer
#define SMEM_PERS   (BBASE + 2 * BBUF_B)   // 205824 B

// ---------------- xproj GEMM SMEM layout ---------------------------------
#define SP          72
#define REG_BYTES   (128 * SP * 2)
#define XBUF_BYTES  (4 * REG_BYTES)
#define SMEM_XP     (2 * XBUF_BYTES)       // 147456 B

// ---------------------------------------------------------------------------
// Persistent device scratch (no cudaMalloc allowed)
// ---------------------------------------------------------------------------
__device__ __align__(16) bf16 g_Whh_hi[(size_t)G4 * Hq];
__device__ __align__(16) bf16 g_Whh_lo[(size_t)G4 * Hq];
__device__ __align__(16) bf16 g_Wih_hi[(size_t)G4 * Iq];
__device__ __align__(16) bf16 g_Wih_lo[(size_t)G4 * Iq];
__device__ __align__(16) bf16 g_x_hi[(size_t)NB * Iq];   // [t*128+b][i]
__device__ __align__(16) bf16 g_x_lo[(size_t)NB * Iq];
__device__ __align__(16) bf16 g_h_hi[2][Bq * Hq];        // [buf][b][k]
__device__ __align__(16) bf16 g_h_lo[2][Bq * Hq];
__device__ float g_hf[Hq * Bq];                          // [u][b] final h
__device__ float g_xp[(size_t)G4 * NB];                  // x-proj [row][t*128+b]
__device__ unsigned g_bar_count;
__device__ unsigned g_bar_gen;

// ---------------------------------------------------------------------------
// PTX helpers (plain sm_100 feature set)
// ---------------------------------------------------------------------------
__device__ __forceinline__ uint32_t smem_u32(const void* p) {
    uint32_t a;
    asm("{ .reg .u64 t; cvta.to.shared.u64 t, %1; cvt.u32.u64 %0, t; }"
        : "=r"(a) : "l"(p));
    return a;
}
__device__ __forceinline__ void ldsm4(uint32_t* r, uint32_t addr) {
    asm volatile("ldmatrix.sync.aligned.m8n8.x4.shared.b16 {%0,%1,%2,%3}, [%4];"
                 : "=r"(r[0]), "=r"(r[1]), "=r"(r[2]), "=r"(r[3]) : "r"(addr));
}
__device__ __forceinline__ void ldsm2(uint32_t* r, uint32_t addr) {
    asm volatile("ldmatrix.sync.aligned.m8n8.x2.shared.b16 {%0,%1}, [%2];"
                 : "=r"(r[0]), "=r"(r[1]) : "r"(addr));
}
__device__ __forceinline__ void mma16816(float* c, const uint32_t* a, const uint32_t* b) {
    asm volatile(
        "mma.sync.aligned.m16n8k16.row.col.f32.bf16.bf16.f32 "
        "{%0,%1,%2,%3}, {%4,%5,%6,%7}, {%8,%9}, {%0,%1,%2,%3};"
        : "+f"(c[0]), "+f"(c[1]), "+f"(c[2]), "+f"(c[3])
        : "r"(a[0]), "r"(a[1]), "r"(a[2]), "r"(a[3]), "r"(b[0]), "r"(b[1]));
}
#define CP16(d, s) \
    asm volatile("cp.async.cg.shared.global [%0], [%1], 16;" :: "r"(d), "l"(s) : "memory")
#define CPCOMMIT() asm volatile("cp.async.commit_group;" ::: "memory")

__device__ __forceinline__ float sigf(float x) { return 1.0f / (1.0f + expf(-x)); }

// sense-reversing grid barrier (all NCTA CTAs co-resident: 1 CTA/SM by SMEM)
__device__ __forceinline__ void gbar() {
    __syncthreads();
    if (threadIdx.x == 0) {
        unsigned gen;
        asm volatile("ld.acquire.gpu.global.u32 %0, [%1];"
                     : "=r"(gen) : "l"(&g_bar_gen) : "memory");
        __threadfence();
        if (atomicAdd(&g_bar_count, 1u) == NCTA - 1) {
            g_bar_count = 0;
            __threadfence();
            asm volatile("st.release.gpu.global.u32 [%0], %1;"
                         :: "l"(&g_bar_gen), "r"(gen + 1) : "memory");
        } else {
            unsigned cur;
            do {
                asm volatile("nanosleep.u32 64;");
                asm volatile("ld.acquire.gpu.global.u32 %0, [%1];"
                             : "=r"(cur) : "l"(&g_bar_gen) : "memory");
            } while (cur == gen);
        }
    }
    __syncthreads();
}

// ---------------------------------------------------------------------------
// Prep kernels
// ---------------------------------------------------------------------------
__global__ void k_prep_w(const float* __restrict__ Wih, const float* __restrict__ Whh) {
    int r = blockIdx.x;
    for (int k = threadIdx.x; k < Hq; k += 256) {
        float w = Whh[(size_t)r * Hq + k];
        bf16 hi = __float2bfloat16(w);
        g_Whh_hi[(size_t)r * Hq + k] = hi;
        g_Whh_lo[(size_t)r * Hq + k] = __float2bfloat16(w - __bfloat162float(hi));
    }
    for (int k = threadIdx.x; k < Iq; k += 256) {
        float w = Wih[(size_t)r * Iq + k];
        bf16 hi = __float2bfloat16(w);
        g_Wih_hi[(size_t)r * Iq + k] = hi;
        g_Wih_lo[(size_t)r * Iq + k] = __float2bfloat16(w - __bfloat162float(hi));
    }
}

__global__ void k_prep_x(const float* __restrict__ XW) {
    int bx = blockIdx.x;          // t*128 + b
    int t = bx >> 7, b = bx & 127;
    const float* __restrict__ src = XW + ((size_t)b * Tq + t) * Iq;
    size_t doff = (size_t)bx * Iq;
    for (int i = threadIdx.x; i < Iq; i += 256) {
        float v = src[i];
        bf16 hi = __float2bfloat16(v);
        g_x_hi[doff + i] = hi;
        g_x_lo[doff + i] = __float2bfloat16(v - __bfloat162float(hi));
    }
}

__global__ void k_init() {
    if (blockIdx.x == 0 && threadIdx.x == 0) {
        g_bar_count = 0;
        g_bar_gen   = 0;
    }
    int n = Bq * Hq;
    for (int i = blockIdx.x * blockDim.x + threadIdx.x; i < n;
         i += gridDim.x * blockDim.x) {
        bf16 z = __float2bfloat16(0.0f);
        g_h_hi[0][i] = z; g_h_lo[0][i] = z;
        g_h_hi[1][i] = z; g_h_lo[1][i] = z;
    }
}

// ---------------------------------------------------------------------------
// x-projection GEMM (bf16 3-term split, mma.sync): g_xp = Wih * x^T
// grid (32, 512): C tile 128(M rows of 4096) x 128(N cols of 65536), K=512.
// ---------------------------------------------------------------------------
__global__ __launch_bounds__(256) void k_xproj() {
    extern __shared__ __align__(128) uint8_t smem[];
    const uint32_t sb = smem_u32(smem);
    const int tid = threadIdx.x;
    const int L = tid & 31, w = tid >> 5;
    const int mw = w & 3, nw = w >> 2;   // warp tile M32 x N64

    const int mrow0 = blockIdx.x * 128;
    const int nrow0 = blockIdx.y * 128;
    const int lsc = tid & 7;

    const uint32_t a_off = ((mw * 32 + (L & 15)) * SP + (L >> 4) * 8) * 2;
    const uint32_t b_off = ((nw * 64 + (L & 7)) * SP + ((L >> 3) & 1) * 8) * 2;

    float acc[2][8][4];
#pragma unroll
    for (int mi = 0; mi < 2; mi++)
#pragma unroll
        for (int nj = 0; nj < 8; nj++)
#pragma unroll
            for (int q = 0; q < 4; q++) acc[mi][nj][q] = 0.0f;

    auto load_chunk = [&](int buf, int ch) {
        const int gk = ch * 64 + lsc * 8;
        const uint32_t dstbase = sb + buf * XBUF_BYTES;
#pragma unroll
        for (int i = 0; i < 4; i++) {
            int row = (tid >> 3) + i * 32;
            uint32_t doff = (uint32_t)row * 144 + lsc * 16;
            size_t ao = (size_t)(mrow0 + row) * Iq + gk;
            size_t bo = (size_t)(nrow0 + row) * Iq + gk;
            CP16(dstbase + 0 * REG_BYTES + doff, g_Wih_hi + ao);
            CP16(dstbase + 1 * REG_BYTES + doff, g_Wih_lo + ao);
            CP16(dstbase + 2 * REG_BYTES + doff, g_x_hi + bo);
            CP16(dstbase + 3 * REG_BYTES + doff, g_x_lo + bo);
        }
        CPCOMMIT();
    };

    load_chunk(0, 0);
    load_chunk(1, 1);
    for (int c = 0; c < 8; c++) {
        if (c < 7) asm volatile("cp.async.wait_group 1;" ::: "memory");
        else       asm volatile("cp.async.wait_group 0;" ::: "memory");
        __syncthreads();
        const uint32_t base = sb + (c & 1) * XBUF_BYTES;
#pragma unroll
        for (int ki = 0; ki < 4; ki++) {
            uint32_t ah[2][4], al[2][4], bh[8][2], bl[8][2];
#pragma unroll
            for (int mi = 0; mi < 2; mi++) {
                uint32_t ad = base + a_off + (mi * 16 * SP + ki * 16) * 2;
                ldsm4(ah[mi], ad);
                ldsm4(al[mi], ad + REG_BYTES);
            }
#pragma unroll
            for (int nj = 0; nj < 8; nj++) {
                uint32_t bd = base + 2 * REG_BYTES + b_off + (nj * 8 * SP + ki * 16) * 2;
                ldsm2(bh[nj], bd);
                ldsm2(bl[nj], bd + REG_BYTES);
            }
#pragma unroll
            for (int mi = 0; mi < 2; mi++)
#pragma unroll
                for (int nj = 0; nj < 8; nj++) {
                    mma16816(acc[mi][nj], ah[mi], bh[nj]);
                    mma16816(acc[mi][nj], ah[mi], bl[nj]);
                    mma16816(acc[mi][nj], al[mi], bh[nj]);
                }
        }
        if (c + 2 < 8) {
            __syncthreads();
            load_chunk(c & 1, c + 2);
        }
    }

#pragma unroll
    for (int mi = 0; mi < 2; mi++)
#pragma unroll
        for (int nj = 0; nj < 8; nj++) {
            int row = mrow0 + mw * 32 + mi * 16 + (L >> 2);
            int col = nrow0 + nw * 64 + nj * 8 + (L & 3) * 2;
            float* p = g_xp + (size_t)row * NB + col;
            *(float2*)p            = make_float2(acc[mi][nj][0], acc[mi][nj][1]);
            *(float2*)(p + 8 * NB) = make_float2(acc[mi][nj][2], acc[mi][nj][3]);
        }
}

// ---------------------------------------------------------------------------
// Persistent recurrence: 128 CTAs x 256 threads, all 512 steps in one launch.
// CTA c owns hidden units u = c*8 .. c*8+7 (32 gate rows: row32 = g*8+j).
// A (Whh splits, 32 rows x K=1024) resident in SMEM. B (h) streamed per step.
// Warp tile: M32 x N16 (8 warps cover N=128). Cell state in registers.
// ---------------------------------------------------------------------------
__global__ __launch_bounds__(256, 1) void k_recur(const float* __restrict__ bih,
                                                  const float* __restrict__ bhh) {
    extern __shared__ __align__(128) uint8_t smem[];
    const uint32_t sb = smem_u32(smem);
    const int tid = threadIdx.x;
    const int c = blockIdx.x;
    const int L = tid & 31;
    const int nw = tid >> 5;             // warp = N group of 16 cols

    // ---- load resident A (Whh hi/lo) : 32 rows x 1024 halves each ----
    {
        int row32 = tid >> 3;            // 0..31
        int g = row32 >> 3, j = row32 & 7;
        size_t grow = ((size_t)g * Hq + c * 8 + j) * Hq;
        int seg = tid & 7;
#pragma unroll
        for (int it = 0; it < 16; it++) {
            int s16 = seg + it * 8;      // 0..127 16B segments per row
            uint32_t doff = (uint32_t)row32 * (PA * 2) + s16 * 16;
            CP16(sb + doff,           g_Whh_hi + grow + s16 * 8);
            CP16(sb + A_SPL_B + doff, g_Whh_lo + grow + s16 * 8);
        }
        CPCOMMIT();
    }

    // per-thread cell mapping
    const int j = (L >> 2) & 7;          // unit within CTA
    const int u = c * 8 + j;             // global hidden unit
    const int c0 = nw * 16 + (L & 3) * 2; // batch col base; cols c0,c0+1,c0+8,c0+9
    float bias[4], cc[4];
#pragma unroll
    for (int g = 0; g < 4; g++) {
        bias[g] = bih[g * Hq + u] + bhh[g * Hq + u];
        cc[g] = 0.0f;                    // cc indexed by (nj*2+e), init 0
    }

    // ldmatrix per-lane offsets
    const uint32_t aoff = (((L & 15) * PA + (L >> 4) * 8)) * 2;
    const uint32_t boff = (((L & 7) * 72 + ((L >> 3) & 1) * 8)) * 2 + nw * 16 * 144;

    asm volatile("cp.async.wait_group 0;" ::: "memory");
    __syncthreads();

    for (int s = 0; s < Tq; s++) {
        const int t = Tq - 1 - s;
        const bf16* __restrict__ hin_hi = g_h_hi[s & 1];
        const bf16* __restrict__ hin_lo = g_h_lo[s & 1];
        bf16* __restrict__ hout_hi = g_h_hi[(s + 1) & 1];
        bf16* __restrict__ hout_lo = g_h_lo[(s + 1) & 1];

        // prefetch x-projection values for this thread's 16 gate outputs
        float2 xp[4][2];
#pragma unroll
        for (int g = 0; g < 4; g++)
#pragma unroll
            for (int nj = 0; nj < 2; nj++)
                xp[g][nj] = *(const float2*)&g_xp[(size_t)(g * Hq + u) * NB
                                                 + t * Bq + c0 + nj * 8];

        float acc[2][2][4];
#pragma unroll
        for (int mi = 0; mi < 2; mi++)
#pragma unroll
            for (int nj = 0; nj < 2; nj++)
#pragma unroll
                for (int q = 0; q < 4; q++) acc[mi][nj][q] = 0.0f;

        auto loadB = [&](int buf, int ch) {
            int b = tid >> 1;
            uint32_t dbase = sb + BBASE + buf * BBUF_B + (uint32_t)b * 144;
            size_t srow = (size_t)b * Hq + ch * 64;
#pragma unroll
            for (int q = 0; q < 4; q++) {
                int sg = (tid & 1) * 4 + q;
                CP16(dbase + sg * 16,        hin_hi + srow + sg * 8);
                CP16(dbase + BSPL + sg * 16, hin_lo + srow + sg * 8);
            }
            CPCOMMIT();
        };

        loadB(0, 0);
        loadB(1, 1);
#pragma unroll 4
        for (int ch = 0; ch < 16; ch++) {
            if (ch < 15) asm volatile("cp.async.wait_group 1;" ::: "memory");
            else         asm volatile("cp.async.wait_group 0;" ::: "memory");
            __syncthreads();
            const uint32_t bbase = sb + BBASE + (ch & 1) * BBUF_B + boff;
#pragma unroll
            for (int ki = 0; ki < 4; ki++) {
                const int k = ch * 64 + ki * 16;
                uint32_t ah[2][4], al[2][4], bh[2][2], bl[2][2];
#pragma unroll
                for (int mi = 0; mi < 2; mi++) {
                    uint32_t ad = sb + aoff + (uint32_t)(mi * 16 * PA + k) * 2;
                    ldsm4(ah[mi], ad);
                    ldsm4(al[mi], ad + A_SPL_B);
                }
#pragma unroll
                for (int nj = 0; nj < 2; nj++) {
                    uint32_t bd = bbase + (uint32_t)(nj * 8) * 144 + ki * 32;
                    ldsm2(bh[nj], bd);
                    ldsm2(bl[nj], bd + BSPL);
                }
#pragma unroll
                for (int mi = 0; mi < 2; mi++)
#pragma unroll
                    for (int nj = 0; nj < 2; nj++) {
                        mma16816(acc[mi][nj], ah[mi], bh[nj]);
                        mma16816(acc[mi][nj], ah[mi], bl[nj]);
                        mma16816(acc[mi][nj], al[mi], bh[nj]);
                    }
            }
            __syncthreads();
            if (ch + 2 < 16) loadB(ch & 1, ch + 2);
        }

        // ---- register-local cell update for 4 (batch) positions ----
        const bool last = (s == Tq - 1);
#pragma unroll
        for (int nj = 0; nj < 2; nj++)
#pragma unroll
            for (int e = 0; e < 2; e++) {
                int b = c0 + nj * 8 + e;
                float xpi = e ? xp[0][nj].y : xp[0][nj].x;
                float xpf = e ? xp[1][nj].y : xp[1][nj].x;
                float xpg = e ? xp[2][nj].y : xp[2][nj].x;
                float xpo = e ? xp[3][nj].y : xp[3][nj].x;
                float ig = sigf(acc[0][nj][e]     + xpi + bias[0]);
                float fg = sigf(acc[0][nj][2 + e] + xpf + bias[1]);
                float gg = tanhf(acc[1][nj][e]    + xpg + bias[2]);
                float og = sigf(acc[1][nj][2 + e] + xpo + bias[3]);
                int ci = nj * 2 + e;
                float cv = fg * cc[ci] + ig * gg;
                cc[ci] = cv;
                float h = og * tanhf(cv);
                bf16 hi = __float2bfloat16(h);
                hout_hi[b * Hq + u] = hi;
                hout_lo[b * Hq + u] = __float2bfloat16(h - __bfloat162float(hi));
                if (last) g_hf[u * Bq + b] = h;
            }

        gbar();
    }
}

// ---------------------------------------------------------------------------
// Final linear
// ---------------------------------------------------------------------------
__global__ __launch_bounds__(256) void k_lin(const float* __restrict__ Wlin,
                                             const float* __restrict__ blin,
                                             float* __restrict__ out) {
    int gid = blockIdx.x * blockDim.x + threadIdx.x;
    int b = gid & (Bq - 1);
    int tgt = gid >> 7;
    float acc = blin[tgt];
    const float* __restrict__ wrow = Wlin + (size_t)tgt * Hq;
#pragma unroll 8
    for (int k = 0; k < Hq; k++) {
        acc += g_hf[k * Bq + b] * wrow[k];
    }
    out[(size_t)b * TGTq + tgt] = acc;
}

// ---------------------------------------------------------------------------
extern "C" void kernel_launch(void* const* d_in, const int* in_sizes, int n_in,
                              void* d_out, int out_size)
{
    const float* XW   = (const float*)d_in[0];
    const float* Wih  = (const float*)d_in[1];
    const float* Whh  = (const float*)d_in[2];
    const float* bih  = (const float*)d_in[3];
    const float* bhh  = (const float*)d_in[4];
    const float* Wlin = (const float*)d_in[5];
    const float* blin = (const float*)d_in[6];
    float* out = (float*)d_out;

    cudaFuncSetAttribute(k_xproj, cudaFuncAttributeMaxDynamicSharedMemorySize, SMEM_XP);
    cudaFuncSetAttribute(k_recur, cudaFuncAttributeMaxDynamicSharedMemorySize, SMEM_PERS);

    k_prep_w<<<G4, 256>>>(Wih, Whh);
    k_prep_x<<<NB, 256>>>(XW);
    k_init<<<128, 256>>>();
    k_xproj<<<dim3(32, 512, 1), 256, SMEM_XP>>>();
    k_recur<<<NCTA, 256, SMEM_PERS>>>(bih, bhh);
    k_lin<<<(Bq * TGTq) / 256, 256>>>(Wlin, blin, out);
}

// round 8
// speedup vs baseline: 2.5011x; 1.1143x over previous
#include <cuda_runtime.h>
#include <cuda_bf16.h>
#include <math.h>
#include <stdint.h>

typedef __nv_bfloat16 bf16;

#define Bq   128
#define Tq   512
#define Iq   512
#define Hq   1024
#define G4   4096
#define TGTq 512
#define NB   65536   // Tq * Bq
#define NCTA 128

// ---------------- persistent-kernel SMEM layout (A resident only) --------
#define PA          1032                   // A row pitch (halves): 1024 + 8 pad
#define A_SPL_B     (32 * PA * 2)          // 66048 B per split
#define SMEM_PERS   (2 * A_SPL_B + 16)     // 132112 B

// ---------------- xproj GEMM SMEM layout ---------------------------------
#define SP          72
#define REG_BYTES   (128 * SP * 2)
#define XBUF_BYTES  (4 * REG_BYTES)
#define SMEM_XP     (2 * XBUF_BYTES)       // 147456 B

// ---------------------------------------------------------------------------
// Persistent device scratch (no cudaMalloc allowed)
// ---------------------------------------------------------------------------
__device__ __align__(16) bf16 g_Whh_hi[(size_t)G4 * Hq];
__device__ __align__(16) bf16 g_Whh_lo[(size_t)G4 * Hq];
__device__ __align__(16) bf16 g_Wih_hi[(size_t)G4 * Iq];
__device__ __align__(16) bf16 g_Wih_lo[(size_t)G4 * Iq];
__device__ __align__(16) bf16 g_x_hi[(size_t)NB * Iq];   // [t*128+b][i]
__device__ __align__(16) bf16 g_x_lo[(size_t)NB * Iq];
// h in mma-B-fragment layout: [buf][(kb*16+bg)*32+lane] = {hi0,hi1,lo0,lo1}
// kb = k-block (16 hidden units), bg = batch group of 8, lane = frag lane.
__device__ __align__(16) uint4 g_hB[2][64 * 16 * 32];
__device__ float g_hf[Hq * Bq];                          // [u][b] final h
__device__ float g_xp[(size_t)G4 * NB];                  // x-proj [row][t*128+b]
__device__ unsigned g_bar_count;
__device__ unsigned g_bar_gen;

// ---------------------------------------------------------------------------
// PTX helpers (plain sm_100 feature set)
// ---------------------------------------------------------------------------
__device__ __forceinline__ uint32_t smem_u32(const void* p) {
    uint32_t a;
    asm("{ .reg .u64 t; cvta.to.shared.u64 t, %1; cvt.u32.u64 %0, t; }"
        : "=r"(a) : "l"(p));
    return a;
}
__device__ __forceinline__ void ldsm4(uint32_t* r, uint32_t addr) {
    asm volatile("ldmatrix.sync.aligned.m8n8.x4.shared.b16 {%0,%1,%2,%3}, [%4];"
                 : "=r"(r[0]), "=r"(r[1]), "=r"(r[2]), "=r"(r[3]) : "r"(addr));
}
__device__ __forceinline__ void ldsm2(uint32_t* r, uint32_t addr) {
    asm volatile("ldmatrix.sync.aligned.m8n8.x2.shared.b16 {%0,%1}, [%2];"
                 : "=r"(r[0]), "=r"(r[1]) : "r"(addr));
}
__device__ __forceinline__ void mma16816(float* c, const uint32_t* a, const uint32_t* b) {
    asm volatile(
        "mma.sync.aligned.m16n8k16.row.col.f32.bf16.bf16.f32 "
        "{%0,%1,%2,%3}, {%4,%5,%6,%7}, {%8,%9}, {%0,%1,%2,%3};"
        : "+f"(c[0]), "+f"(c[1]), "+f"(c[2]), "+f"(c[3])
        : "r"(a[0]), "r"(a[1]), "r"(a[2]), "r"(a[3]), "r"(b[0]), "r"(b[1]));
}
__device__ __forceinline__ void ldg_cg_v4(uint4& v, const uint4* p) {
    asm volatile("ld.global.cg.v4.u32 {%0,%1,%2,%3}, [%4];"
                 : "=r"(v.x), "=r"(v.y), "=r"(v.z), "=r"(v.w) : "l"(p));
}
#define CP16(d, s) \
    asm volatile("cp.async.cg.shared.global [%0], [%1], 16;" :: "r"(d), "l"(s) : "memory")
#define CPCOMMIT() asm volatile("cp.async.commit_group;" ::: "memory")

__device__ __forceinline__ float sigf(float x) { return 1.0f / (1.0f + expf(-x)); }

// sense-reversing grid barrier (all NCTA CTAs co-resident: 1 CTA/SM by SMEM)
__device__ __forceinline__ void gbar() {
    __syncthreads();
    if (threadIdx.x == 0) {
        unsigned gen;
        asm volatile("ld.acquire.gpu.global.u32 %0, [%1];"
                     : "=r"(gen) : "l"(&g_bar_gen) : "memory");
        __threadfence();
        if (atomicAdd(&g_bar_count, 1u) == NCTA - 1) {
            g_bar_count = 0;
            __threadfence();
            asm volatile("st.release.gpu.global.u32 [%0], %1;"
                         :: "l"(&g_bar_gen), "r"(gen + 1) : "memory");
        } else {
            unsigned cur;
            do {
                asm volatile("nanosleep.u32 64;");
                asm volatile("ld.acquire.gpu.global.u32 %0, [%1];"
                             : "=r"(cur) : "l"(&g_bar_gen) : "memory");
            } while (cur == gen);
        }
    }
    __syncthreads();
}

// ---------------------------------------------------------------------------
// Prep kernels
// ---------------------------------------------------------------------------
__global__ void k_prep_w(const float* __restrict__ Wih, const float* __restrict__ Whh) {
    int r = blockIdx.x;
    for (int k = threadIdx.x; k < Hq; k += 256) {
        float w = Whh[(size_t)r * Hq + k];
        bf16 hi = __float2bfloat16(w);
        g_Whh_hi[(size_t)r * Hq + k] = hi;
        g_Whh_lo[(size_t)r * Hq + k] = __float2bfloat16(w - __bfloat162float(hi));
    }
    for (int k = threadIdx.x; k < Iq; k += 256) {
        float w = Wih[(size_t)r * Iq + k];
        bf16 hi = __float2bfloat16(w);
        g_Wih_hi[(size_t)r * Iq + k] = hi;
        g_Wih_lo[(size_t)r * Iq + k] = __float2bfloat16(w - __bfloat162float(hi));
    }
}

__global__ void k_prep_x(const float* __restrict__ XW) {
    int bx = blockIdx.x;          // t*128 + b
    int t = bx >> 7, b = bx & 127;
    const float* __restrict__ src = XW + ((size_t)b * Tq + t) * Iq;
    size_t doff = (size_t)bx * Iq;
    for (int i = threadIdx.x; i < Iq; i += 256) {
        float v = src[i];
        bf16 hi = __float2bfloat16(v);
        g_x_hi[doff + i] = hi;
        g_x_lo[doff + i] = __float2bfloat16(v - __bfloat162float(hi));
    }
}

__global__ void k_init() {
    if (blockIdx.x == 0 && threadIdx.x == 0) {
        g_bar_count = 0;
        g_bar_gen   = 0;
    }
    int n = 64 * 16 * 32;  // uint4 count per buffer
    uint4 z = make_uint4(0, 0, 0, 0);
    for (int i = blockIdx.x * blockDim.x + threadIdx.x; i < n;
         i += gridDim.x * blockDim.x) {
        g_hB[0][i] = z;
        g_hB[1][i] = z;
    }
}

// ---------------------------------------------------------------------------
// x-projection GEMM (bf16 3-term split, mma.sync): g_xp = Wih * x^T
// grid (32, 512): C tile 128(M rows of 4096) x 128(N cols of 65536), K=512.
// ---------------------------------------------------------------------------
__global__ __launch_bounds__(256) void k_xproj() {
    extern __shared__ __align__(128) uint8_t smem[];
    const uint32_t sb = smem_u32(smem);
    const int tid = threadIdx.x;
    const int L = tid & 31, w = tid >> 5;
    const int mw = w & 3, nw = w >> 2;   // warp tile M32 x N64

    const int mrow0 = blockIdx.x * 128;
    const int nrow0 = blockIdx.y * 128;
    const int lsc = tid & 7;

    const uint32_t a_off = ((mw * 32 + (L & 15)) * SP + (L >> 4) * 8) * 2;
    const uint32_t b_off = ((nw * 64 + (L & 7)) * SP + ((L >> 3) & 1) * 8) * 2;

    float acc[2][8][4];
#pragma unroll
    for (int mi = 0; mi < 2; mi++)
#pragma unroll
        for (int nj = 0; nj < 8; nj++)
#pragma unroll
            for (int q = 0; q < 4; q++) acc[mi][nj][q] = 0.0f;

    auto load_chunk = [&](int buf, int ch) {
        const int gk = ch * 64 + lsc * 8;
        const uint32_t dstbase = sb + buf * XBUF_BYTES;
#pragma unroll
        for (int i = 0; i < 4; i++) {
            int row = (tid >> 3) + i * 32;
            uint32_t doff = (uint32_t)row * 144 + lsc * 16;
            size_t ao = (size_t)(mrow0 + row) * Iq + gk;
            size_t bo = (size_t)(nrow0 + row) * Iq + gk;
            CP16(dstbase + 0 * REG_BYTES + doff, g_Wih_hi + ao);
            CP16(dstbase + 1 * REG_BYTES + doff, g_Wih_lo + ao);
            CP16(dstbase + 2 * REG_BYTES + doff, g_x_hi + bo);
            CP16(dstbase + 3 * REG_BYTES + doff, g_x_lo + bo);
        }
        CPCOMMIT();
    };

    load_chunk(0, 0);
    load_chunk(1, 1);
    for (int c = 0; c < 8; c++) {
        if (c < 7) asm volatile("cp.async.wait_group 1;" ::: "memory");
        else       asm volatile("cp.async.wait_group 0;" ::: "memory");
        __syncthreads();
        const uint32_t base = sb + (c & 1) * XBUF_BYTES;
#pragma unroll
        for (int ki = 0; ki < 4; ki++) {
            uint32_t ah[2][4], al[2][4], bh[8][2], bl[8][2];
#pragma unroll
            for (int mi = 0; mi < 2; mi++) {
                uint32_t ad = base + a_off + (mi * 16 * SP + ki * 16) * 2;
                ldsm4(ah[mi], ad);
                ldsm4(al[mi], ad + REG_BYTES);
            }
#pragma unroll
            for (int nj = 0; nj < 8; nj++) {
                uint32_t bd = base + 2 * REG_BYTES + b_off + (nj * 8 * SP + ki * 16) * 2;
                ldsm2(bh[nj], bd);
                ldsm2(bl[nj], bd + REG_BYTES);
            }
#pragma unroll
            for (int mi = 0; mi < 2; mi++)
#pragma unroll
                for (int nj = 0; nj < 8; nj++) {
                    mma16816(acc[mi][nj], ah[mi], bh[nj]);
                    mma16816(acc[mi][nj], ah[mi], bl[nj]);
                    mma16816(acc[mi][nj], al[mi], bh[nj]);
                }
        }
        if (c + 2 < 8) {
            __syncthreads();
            load_chunk(c & 1, c + 2);
        }
    }

#pragma unroll
    for (int mi = 0; mi < 2; mi++)
#pragma unroll
        for (int nj = 0; nj < 8; nj++) {
            int row = mrow0 + mw * 32 + mi * 16 + (L >> 2);
            int col = nrow0 + nw * 64 + nj * 8 + (L & 3) * 2;
            float* p = g_xp + (size_t)row * NB + col;
            *(float2*)p            = make_float2(acc[mi][nj][0], acc[mi][nj][1]);
            *(float2*)(p + 8 * NB) = make_float2(acc[mi][nj][2], acc[mi][nj][3]);
        }
}

// ---------------------------------------------------------------------------
// Persistent recurrence. CTA c owns hidden units u = c*8..c*8+7 (32 gate rows).
// A (Whh splits) resident in SMEM; B (h) read as fragment quads via ld.cg —
// no B staging, no intra-step __syncthreads. Cell state in registers; next-step
// h written directly in B-fragment layout.
// ---------------------------------------------------------------------------
__global__ __launch_bounds__(256, 1) void k_recur(const float* __restrict__ bih,
                                                  const float* __restrict__ bhh) {
    extern __shared__ __align__(128) uint8_t smem[];
    const uint32_t sb = smem_u32(smem);
    const int tid = threadIdx.x;
    const int c = blockIdx.x;
    const int L = tid & 31;
    const int nw = tid >> 5;             // warp = N group of 16 batch cols

    // ---- load resident A (Whh hi/lo) : 32 rows x 1024 halves each ----
    {
        int row32 = tid >> 3;            // 0..31
        int g = row32 >> 3, j = row32 & 7;
        size_t grow = ((size_t)g * Hq + c * 8 + j) * Hq;
        int seg = tid & 7;
#pragma unroll
        for (int it = 0; it < 16; it++) {
            int s16 = seg + it * 8;      // 0..127 16B segments per row
            uint32_t doff = (uint32_t)row32 * (PA * 2) + s16 * 16;
            CP16(sb + doff,           g_Whh_hi + grow + s16 * 8);
            CP16(sb + A_SPL_B + doff, g_Whh_lo + grow + s16 * 8);
        }
        CPCOMMIT();
    }

    // per-thread cell mapping
    const int j = (L >> 2) & 7;          // unit within CTA
    const int u = c * 8 + j;             // global hidden unit
    const int c0 = nw * 16 + (L & 3) * 2; // batch cols c0,c0+1,c0+8,c0+9
    float bias[4], cc[4];
#pragma unroll
    for (int g = 0; g < 4; g++) {
        bias[g] = bih[g * Hq + u] + bhh[g * Hq + u];
        cc[g] = 0.0f;                    // cc indexed by (nj*2+e)
    }

    // producer store mapping for h fragments (8 2B stores per thread)
    const int p_kb  = u >> 4;
    const int p_ln  = ((u >> 1) & 3);    // lane bits from unit
    const int p_boff = ((u >> 3) & 1) * 4 + (u & 1) * 2; // byte offset in quad (hi)

    // ldmatrix per-lane A offset
    const uint32_t aoff = (((L & 15) * PA + (L >> 4) * 8)) * 2;
    const int bgBase = nw * 2;           // batch groups for this warp

    asm volatile("cp.async.wait_group 0;" ::: "memory");
    __syncthreads();

    for (int s = 0; s < Tq; s++) {
        const int t = Tq - 1 - s;
        const uint4* __restrict__ hBin = g_hB[s & 1];
        uint4* __restrict__ hBout      = g_hB[(s + 1) & 1];

        // prefetch x-projection values for this thread's 16 gate outputs
        float2 xp[4][2];
#pragma unroll
        for (int g = 0; g < 4; g++)
#pragma unroll
            for (int nj = 0; nj < 2; nj++)
                xp[g][nj] = *(const float2*)&g_xp[(size_t)(g * Hq + u) * NB
                                                 + t * Bq + c0 + nj * 8];

        float acc[2][2][4];
#pragma unroll
        for (int mi = 0; mi < 2; mi++)
#pragma unroll
            for (int nj = 0; nj < 2; nj++)
#pragma unroll
                for (int q = 0; q < 4; q++) acc[mi][nj][q] = 0.0f;

        // B fragment register pipeline: groups of 4 kb, prefetch depth 2
        uint4 Bp[3][8];
        auto loadBgrp = [&](int g, int slot) {
#pragma unroll
            for (int kk = 0; kk < 4; kk++)
#pragma unroll
                for (int nj = 0; nj < 2; nj++) {
                    int kb = g * 4 + kk;
                    ldg_cg_v4(Bp[slot][kk * 2 + nj],
                              hBin + ((kb * 16 + bgBase + nj) * 32 + L));
                }
        };

        loadBgrp(0, 0);
        loadBgrp(1, 1);
        for (int g = 0; g < 16; g++) {
            if (g + 2 < 16) loadBgrp(g + 2, (g + 2) % 3);
            const int slot = g % 3;
#pragma unroll
            for (int kk = 0; kk < 4; kk++) {
                const int k = (g * 4 + kk) * 16;
                uint32_t ah[2][4], al[2][4];
#pragma unroll
                for (int mi = 0; mi < 2; mi++) {
                    uint32_t ad = sb + aoff + (uint32_t)(mi * 16 * PA + k) * 2;
                    ldsm4(ah[mi], ad);
                    ldsm4(al[mi], ad + A_SPL_B);
                }
#pragma unroll
                for (int nj = 0; nj < 2; nj++) {
                    uint32_t bh[2] = { Bp[slot][kk * 2 + nj].x, Bp[slot][kk * 2 + nj].y };
                    uint32_t bl[2] = { Bp[slot][kk * 2 + nj].z, Bp[slot][kk * 2 + nj].w };
#pragma unroll
                    for (int mi = 0; mi < 2; mi++) {
                        mma16816(acc[mi][nj], ah[mi], bh);
                        mma16816(acc[mi][nj], ah[mi], bl);
                        mma16816(acc[mi][nj], al[mi], bh);
                    }
                }
            }
        }

        // ---- register-local cell update for 4 (batch) positions ----
        const bool last = (s == Tq - 1);
#pragma unroll
        for (int nj = 0; nj < 2; nj++)
#pragma unroll
            for (int e = 0; e < 2; e++) {
                int b = c0 + nj * 8 + e;
                float xpi = e ? xp[0][nj].y : xp[0][nj].x;
                float xpf = e ? xp[1][nj].y : xp[1][nj].x;
                float xpg = e ? xp[2][nj].y : xp[2][nj].x;
                float xpo = e ? xp[3][nj].y : xp[3][nj].x;
                float ig = sigf(acc[0][nj][e]     + xpi + bias[0]);
                float fg = sigf(acc[0][nj][2 + e] + xpf + bias[1]);
                float gg = tanhf(acc[1][nj][e]    + xpg + bias[2]);
                float og = sigf(acc[1][nj][2 + e] + xpo + bias[3]);
                int ci = nj * 2 + e;
                float cv = fg * cc[ci] + ig * gg;
                cc[ci] = cv;
                float h = og * tanhf(cv);
                bf16 hi = __float2bfloat16(h);
                bf16 lo = __float2bfloat16(h - __bfloat162float(hi));
                // write into B-fragment layout: quad index (p_kb*16 + b>>3)*32 + lane
                int lane = ((b & 7) << 2) | p_ln;
                char* qp = (char*)&hBout[(p_kb * 16 + (b >> 3)) * 32 + lane];
                *(bf16*)(qp + p_boff)     = hi;
                *(bf16*)(qp + p_boff + 8) = lo;
                if (last) g_hf[u * Bq + b] = h;
            }

        gbar();
    }
}

// ---------------------------------------------------------------------------
// Final linear
// ---------------------------------------------------------------------------
__global__ __launch_bounds__(256) void k_lin(const float* __restrict__ Wlin,
                                             const float* __restrict__ blin,
                                             float* __restrict__ out) {
    int gid = blockIdx.x * blockDim.x + threadIdx.x;
    int b = gid & (Bq - 1);
    int tgt = gid >> 7;
    float acc = blin[tgt];
    const float* __restrict__ wrow = Wlin + (size_t)tgt * Hq;
#pragma unroll 8
    for (int k = 0; k < Hq; k++) {
        acc += g_hf[k * Bq + b] * wrow[k];
    }
    out[(size_t)b * TGTq + tgt] = acc;
}

// ---------------------------------------------------------------------------
extern "C" void kernel_launch(void* const* d_in, const int* in_sizes, int n_in,
                              void* d_out, int out_size)
{
    const float* XW   = (const float*)d_in[0];
    const float* Wih  = (const float*)d_in[1];
    const float* Whh  = (const float*)d_in[2];
    const float* bih  = (const float*)d_in[3];
    const float* bhh  = (const float*)d_in[4];
    const float* Wlin = (const float*)d_in[5];
    const float* blin = (const float*)d_in[6];
    float* out = (float*)d_out;

    cudaFuncSetAttribute(k_xproj, cudaFuncAttributeMaxDynamicSharedMemorySize, SMEM_XP);
    cudaFuncSetAttribute(k_recur, cudaFuncAttributeMaxDynamicSharedMemorySize, SMEM_PERS);

    k_prep_w<<<G4, 256>>>(Wih, Whh);
    k_prep_x<<<NB, 256>>>(XW);
    k_init<<<128, 256>>>();
    k_xproj<<<dim3(32, 512, 1), 256, SMEM_XP>>>();
    k_recur<<<NCTA, 256, SMEM_PERS>>>(bih, bhh);
    k_lin<<<(Bq * TGTq) / 256, 256>>>(Wlin, blin, out);
}

// round 9
// speedup vs baseline: 4.9676x; 1.9862x over previous
#include <cuda_runtime.h>
#include <cuda_fp16.h>
#include <math.h>
#include <stdint.h>

#define Bq   128
#define Tq   512
#define Iq   512
#define Hq   1024
#define G4   4096
#define TGTq 512
#define NB   65536   // Tq * Bq
#define NCTA 128

// ---------------- persistent-kernel SMEM layout (A resident only) --------
#define PA          1032                   // A row pitch (halves): 1024 + 8 pad
#define A_SPL_B     (32 * PA * 2)          // 66048 B per split
#define SMEM_PERS   (2 * A_SPL_B + 16)     // 132112 B

// ---------------- xproj GEMM SMEM layout ---------------------------------
#define SP          72
#define REG_BYTES   (128 * SP * 2)         // 18432
#define XBUF_BYTES  (3 * REG_BYTES)        // Ah, Al, Bx
#define SMEM_XP     (2 * XBUF_BYTES)       // 110592 B

// ---------------------------------------------------------------------------
// Persistent device scratch (no cudaMalloc allowed)
// ---------------------------------------------------------------------------
__device__ __align__(16) __half g_Wr_h[(size_t)G4 * Hq];   // Whh hi (fp16)
__device__ __align__(16) __half g_Wr_l[(size_t)G4 * Hq];   // Whh lo
__device__ __align__(16) __half g_Wi_h[(size_t)G4 * Iq];   // Wih hi
__device__ __align__(16) __half g_Wi_l[(size_t)G4 * Iq];   // Wih lo
__device__ __align__(16) __half g_xh[(size_t)NB * Iq];     // x fp16 [t*128+b][i]
// h in mma-B-fragment layout (fp16 single): [buf][(kb*16+bg)*32+lane] = {r0,r1}
__device__ __align__(16) uint2 g_hB[2][64 * 16 * 32];
__device__ float g_hf[Hq * Bq];                            // [u][b] final h
__device__ float g_xp[(size_t)G4 * NB];                    // x-proj [row][t*128+b]
__device__ unsigned g_cnt[8];
__device__ unsigned g_cnt2;
__device__ unsigned g_gen;

// ---------------------------------------------------------------------------
// PTX helpers (plain sm_100 feature set)
// ---------------------------------------------------------------------------
__device__ __forceinline__ uint32_t smem_u32(const void* p) {
    uint32_t a;
    asm("{ .reg .u64 t; cvta.to.shared.u64 t, %1; cvt.u32.u64 %0, t; }"
        : "=r"(a) : "l"(p));
    return a;
}
__device__ __forceinline__ void ldsm4(uint32_t* r, uint32_t addr) {
    asm volatile("ldmatrix.sync.aligned.m8n8.x4.shared.b16 {%0,%1,%2,%3}, [%4];"
                 : "=r"(r[0]), "=r"(r[1]), "=r"(r[2]), "=r"(r[3]) : "r"(addr));
}
__device__ __forceinline__ void ldsm2(uint32_t* r, uint32_t addr) {
    asm volatile("ldmatrix.sync.aligned.m8n8.x2.shared.b16 {%0,%1}, [%2];"
                 : "=r"(r[0]), "=r"(r[1]) : "r"(addr));
}
__device__ __forceinline__ void mma16816(float* c, const uint32_t* a, const uint32_t* b) {
    asm volatile(
        "mma.sync.aligned.m16n8k16.row.col.f32.f16.f16.f32 "
        "{%0,%1,%2,%3}, {%4,%5,%6,%7}, {%8,%9}, {%0,%1,%2,%3};"
        : "+f"(c[0]), "+f"(c[1]), "+f"(c[2]), "+f"(c[3])
        : "r"(a[0]), "r"(a[1]), "r"(a[2]), "r"(a[3]), "r"(b[0]), "r"(b[1]));
}
__device__ __forceinline__ void ldg_cg_v2(uint2& v, const uint2* p) {
    asm volatile("ld.global.cg.v2.u32 {%0,%1}, [%2];"
                 : "=r"(v.x), "=r"(v.y) : "l"(p));
}
#define CP16(d, s) \
    asm volatile("cp.async.cg.shared.global [%0], [%1], 16;" :: "r"(d), "l"(s) : "memory")
#define CPCOMMIT() asm volatile("cp.async.commit_group;" ::: "memory")

__device__ __forceinline__ float sigf(float x) {
    return __fdividef(1.0f, 1.0f + __expf(-x));
}
__device__ __forceinline__ float tanhfast(float x) {
    return __fdividef(2.0f, 1.0f + __expf(-2.0f * x)) - 1.0f;
}

// two-level sense-reversing grid barrier (8 groups of 16 CTAs)
__device__ __forceinline__ void gbar() {
    __syncthreads();
    if (threadIdx.x == 0) {
        unsigned gen;
        asm volatile("ld.acquire.gpu.global.u32 %0, [%1];"
                     : "=r"(gen) : "l"(&g_gen) : "memory");
        __threadfence();
        unsigned grp = blockIdx.x >> 4;
        if (atomicAdd(&g_cnt[grp], 1u) == 15u) {
            atomicExch(&g_cnt[grp], 0u);
            if (atomicAdd(&g_cnt2, 1u) == 7u) {
                atomicExch(&g_cnt2, 0u);
                __threadfence();
                asm volatile("st.release.gpu.global.u32 [%0], %1;"
                             :: "l"(&g_gen), "r"(gen + 1) : "memory");
            }
        }
        unsigned cur;
        do {
            asm volatile("ld.acquire.gpu.global.u32 %0, [%1];"
                         : "=r"(cur) : "l"(&g_gen) : "memory");
            if (cur != gen) break;
            asm volatile("nanosleep.u32 32;");
        } while (1);
    }
    __syncthreads();
}

// ---------------------------------------------------------------------------
// Prep kernels
// ---------------------------------------------------------------------------
__global__ void k_prep_w(const float* __restrict__ Wih, const float* __restrict__ Whh) {
    int r = blockIdx.x;
    for (int k = threadIdx.x; k < Hq; k += 256) {
        float w = Whh[(size_t)r * Hq + k];
        __half hi = __float2half_rn(w);
        g_Wr_h[(size_t)r * Hq + k] = hi;
        g_Wr_l[(size_t)r * Hq + k] = __float2half_rn(w - __half2float(hi));
    }
    for (int k = threadIdx.x; k < Iq; k += 256) {
        float w = Wih[(size_t)r * Iq + k];
        __half hi = __float2half_rn(w);
        g_Wi_h[(size_t)r * Iq + k] = hi;
        g_Wi_l[(size_t)r * Iq + k] = __float2half_rn(w - __half2float(hi));
    }
}

__global__ void k_prep_x(const float* __restrict__ XW) {
    int bx = blockIdx.x;          // t*128 + b
    int t = bx >> 7, b = bx & 127;
    const float* __restrict__ src = XW + ((size_t)b * Tq + t) * Iq;
    size_t doff = (size_t)bx * Iq;
    for (int i = threadIdx.x; i < Iq; i += 256) {
        g_xh[doff + i] = __float2half_rn(src[i]);
    }
}

__global__ void k_init() {
    if (blockIdx.x == 0 && threadIdx.x < 8) g_cnt[threadIdx.x] = 0;
    if (blockIdx.x == 0 && threadIdx.x == 8) { g_cnt2 = 0; g_gen = 0; }
    int n = 64 * 16 * 32;
    uint2 z = make_uint2(0, 0);
    for (int i = blockIdx.x * blockDim.x + threadIdx.x; i < n;
         i += gridDim.x * blockDim.x) {
        g_hB[0][i] = z;
        g_hB[1][i] = z;
    }
}

// ---------------------------------------------------------------------------
// x-projection GEMM (fp16 2-term split): g_xp = Wih * x^T
// grid (32, 512): C tile 128(M of 4096) x 128(N of 65536), K=512.
// ---------------------------------------------------------------------------
__global__ __launch_bounds__(256) void k_xproj() {
    extern __shared__ __align__(128) uint8_t smem[];
    const uint32_t sb = smem_u32(smem);
    const int tid = threadIdx.x;
    const int L = tid & 31, w = tid >> 5;
    const int mw = w & 3, nw = w >> 2;   // warp tile M32 x N64

    const int mrow0 = blockIdx.x * 128;
    const int nrow0 = blockIdx.y * 128;
    const int lsc = tid & 7;

    const uint32_t a_off = ((mw * 32 + (L & 15)) * SP + (L >> 4) * 8) * 2;
    const uint32_t b_off = ((nw * 64 + (L & 7)) * SP + ((L >> 3) & 1) * 8) * 2;

    float acc[2][8][4];
#pragma unroll
    for (int mi = 0; mi < 2; mi++)
#pragma unroll
        for (int nj = 0; nj < 8; nj++)
#pragma unroll
            for (int q = 0; q < 4; q++) acc[mi][nj][q] = 0.0f;

    auto load_chunk = [&](int buf, int ch) {
        const int gk = ch * 64 + lsc * 8;
        const uint32_t dstbase = sb + buf * XBUF_BYTES;
#pragma unroll
        for (int i = 0; i < 4; i++) {
            int row = (tid >> 3) + i * 32;
            uint32_t doff = (uint32_t)row * 144 + lsc * 16;
            size_t ao = (size_t)(mrow0 + row) * Iq + gk;
            size_t bo = (size_t)(nrow0 + row) * Iq + gk;
            CP16(dstbase + 0 * REG_BYTES + doff, g_Wi_h + ao);
            CP16(dstbase + 1 * REG_BYTES + doff, g_Wi_l + ao);
            CP16(dstbase + 2 * REG_BYTES + doff, g_xh + bo);
        }
        CPCOMMIT();
    };

    load_chunk(0, 0);
    load_chunk(1, 1);
    for (int c = 0; c < 8; c++) {
        if (c < 7) asm volatile("cp.async.wait_group 1;" ::: "memory");
        else       asm volatile("cp.async.wait_group 0;" ::: "memory");
        __syncthreads();
        const uint32_t base = sb + (c & 1) * XBUF_BYTES;
#pragma unroll
        for (int ki = 0; ki < 4; ki++) {
            uint32_t ah[2][4], al[2][4], bh[8][2];
#pragma unroll
            for (int mi = 0; mi < 2; mi++) {
                uint32_t ad = base + a_off + (mi * 16 * SP + ki * 16) * 2;
                ldsm4(ah[mi], ad);
                ldsm4(al[mi], ad + REG_BYTES);
            }
#pragma unroll
            for (int nj = 0; nj < 8; nj++) {
                uint32_t bd = base + 2 * REG_BYTES + b_off + (nj * 8 * SP + ki * 16) * 2;
                ldsm2(bh[nj], bd);
            }
#pragma unroll
            for (int mi = 0; mi < 2; mi++)
#pragma unroll
                for (int nj = 0; nj < 8; nj++) {
                    mma16816(acc[mi][nj], ah[mi], bh[nj]);
                    mma16816(acc[mi][nj], al[mi], bh[nj]);
                }
        }
        if (c + 2 < 8) {
            __syncthreads();
            load_chunk(c & 1, c + 2);
        }
    }

#pragma unroll
    for (int mi = 0; mi < 2; mi++)
#pragma unroll
        for (int nj = 0; nj < 8; nj++) {
            int row = mrow0 + mw * 32 + mi * 16 + (L >> 2);
            int col = nrow0 + nw * 64 + nj * 8 + (L & 3) * 2;
            float* p = g_xp + (size_t)row * NB + col;
            *(float2*)p            = make_float2(acc[mi][nj][0], acc[mi][nj][1]);
            *(float2*)(p + 8 * NB) = make_float2(acc[mi][nj][2], acc[mi][nj][3]);
        }
}

// ---------------------------------------------------------------------------
// Persistent recurrence. CTA c owns hidden units u = c*8..c*8+7 (32 gate rows).
// A (Whh fp16 hi/lo) resident in SMEM; B (h, single fp16) read as fragment
// pairs via ld.cg into a FULLY UNROLLED register ring. Cell state in regs;
// next-step h written directly in B-fragment layout.
// ---------------------------------------------------------------------------
__global__ __launch_bounds__(256, 1) void k_recur(const float* __restrict__ bih,
                                                  const float* __restrict__ bhh) {
    extern __shared__ __align__(128) uint8_t smem[];
    const uint32_t sb = smem_u32(smem);
    const int tid = threadIdx.x;
    const int c = blockIdx.x;
    const int L = tid & 31;
    const int nw = tid >> 5;             // warp = N group of 16 batch cols

    // ---- load resident A (Whh hi/lo) : 32 rows x 1024 halves each ----
    {
        int row32 = tid >> 3;            // 0..31
        int g = row32 >> 3, j = row32 & 7;
        size_t grow = ((size_t)g * Hq + c * 8 + j) * Hq;
        int seg = tid & 7;
#pragma unroll
        for (int it = 0; it < 16; it++) {
            int s16 = seg + it * 8;
            uint32_t doff = (uint32_t)row32 * (PA * 2) + s16 * 16;
            CP16(sb + doff,           g_Wr_h + grow + s16 * 8);
            CP16(sb + A_SPL_B + doff, g_Wr_l + grow + s16 * 8);
        }
        CPCOMMIT();
    }

    // per-thread cell mapping
    const int j = (L >> 2) & 7;          // unit within CTA
    const int u = c * 8 + j;             // global hidden unit
    const int c0 = nw * 16 + (L & 3) * 2; // batch cols c0,c0+1,c0+8,c0+9
    float bias[4], cc[4];
#pragma unroll
    for (int g = 0; g < 4; g++) {
        bias[g] = bih[g * Hq + u] + bhh[g * Hq + u];
        cc[g] = 0.0f;                    // cc indexed by (nj*2+e)
    }

    // producer store mapping for h fragments
    const int p_kb   = u >> 4;
    const int p_ln   = ((u >> 1) & 3);
    const int p_boff = ((u >> 3) & 1) * 4 + (u & 1) * 2;

    const uint32_t aoff = (((L & 15) * PA + (L >> 4) * 8)) * 2;
    const int bgBase = nw * 2;

    asm volatile("cp.async.wait_group 0;" ::: "memory");
    __syncthreads();

    // xp prefetch for first step
    float2 xpv[4][2];
#pragma unroll
    for (int g = 0; g < 4; g++)
#pragma unroll
        for (int nj = 0; nj < 2; nj++)
            xpv[g][nj] = *(const float2*)&g_xp[(size_t)(g * Hq + u) * NB
                                               + (Tq - 1) * Bq + c0 + nj * 8];

    for (int s = 0; s < Tq; s++) {
        const uint2* __restrict__ hBin = g_hB[s & 1];
        uint2* __restrict__ hBout      = g_hB[(s + 1) & 1];

        float acc[2][2][4];
#pragma unroll
        for (int mi = 0; mi < 2; mi++)
#pragma unroll
            for (int nj = 0; nj < 2; nj++)
#pragma unroll
                for (int q = 0; q < 4; q++) acc[mi][nj][q] = 0.0f;

        uint2 Bp[4][8];   // 4-slot ring, fully unrolled indices only

#define LOADB(G, SLOT)                                                        \
        {                                                                     \
            _Pragma("unroll")                                                 \
            for (int kk = 0; kk < 4; kk++)                                    \
                _Pragma("unroll")                                             \
                for (int nj = 0; nj < 2; nj++)                                \
                    ldg_cg_v2(Bp[SLOT][kk * 2 + nj],                          \
                              hBin + (((G) * 4 + kk) * 16 + bgBase + nj) * 32 + L); \
        }

        LOADB(0, 0); LOADB(1, 1); LOADB(2, 2);

#pragma unroll
        for (int g = 0; g < 16; g++) {
            if (g + 3 < 16) {
                const int ng = g + 3;
                const int ns = ng & 3;
                LOADB(ng, ns);
            }
            const int slot = g & 3;
#pragma unroll
            for (int kk = 0; kk < 4; kk++) {
                const int k = (g * 4 + kk) * 16;
                uint32_t ah[2][4], al[2][4];
#pragma unroll
                for (int mi = 0; mi < 2; mi++) {
                    uint32_t ad = sb + aoff + (uint32_t)(mi * 16 * PA + k) * 2;
                    ldsm4(ah[mi], ad);
                    ldsm4(al[mi], ad + A_SPL_B);
                }
#pragma unroll
                for (int nj = 0; nj < 2; nj++) {
                    uint32_t bh[2] = { Bp[slot][kk * 2 + nj].x, Bp[slot][kk * 2 + nj].y };
#pragma unroll
                    for (int mi = 0; mi < 2; mi++) {
                        mma16816(acc[mi][nj], ah[mi], bh);
                        mma16816(acc[mi][nj], al[mi], bh);
                    }
                }
            }
        }
#undef LOADB

        // ---- register-local cell update for 4 (batch) positions ----
        const bool last = (s == Tq - 1);
#pragma unroll
        for (int nj = 0; nj < 2; nj++)
#pragma unroll
            for (int e = 0; e < 2; e++) {
                int b = c0 + nj * 8 + e;
                float xpi = e ? xpv[0][nj].y : xpv[0][nj].x;
                float xpf = e ? xpv[1][nj].y : xpv[1][nj].x;
                float xpg = e ? xpv[2][nj].y : xpv[2][nj].x;
                float xpo = e ? xpv[3][nj].y : xpv[3][nj].x;
                float ig = sigf(acc[0][nj][e]     + xpi + bias[0]);
                float fg = sigf(acc[0][nj][2 + e] + xpf + bias[1]);
                float gg = tanhfast(acc[1][nj][e]    + xpg + bias[2]);
                float og = sigf(acc[1][nj][2 + e] + xpo + bias[3]);
                int ci = nj * 2 + e;
                float cv = fg * cc[ci] + ig * gg;
                cc[ci] = cv;
                float h = og * tanhfast(cv);
                int lane = ((b & 7) << 2) | p_ln;
                char* qp = (char*)&hBout[(p_kb * 16 + (b >> 3)) * 32 + lane];
                *(__half*)(qp + p_boff) = __float2half_rn(h);
                if (last) g_hf[u * Bq + b] = h;
            }

        // prefetch next step's xp before the barrier (read-only, precomputed)
        if (!last) {
            const int tn = Tq - 2 - s;
#pragma unroll
            for (int g = 0; g < 4; g++)
#pragma unroll
                for (int nj = 0; nj < 2; nj++)
                    xpv[g][nj] = *(const float2*)&g_xp[(size_t)(g * Hq + u) * NB
                                                       + tn * Bq + c0 + nj * 8];
            gbar();
        }
    }
}

// ---------------------------------------------------------------------------
// Final linear
// ---------------------------------------------------------------------------
__global__ __launch_bounds__(256) void k_lin(const float* __restrict__ Wlin,
                                             const float* __restrict__ blin,
                                             float* __restrict__ out) {
    int gid = blockIdx.x * blockDim.x + threadIdx.x;
    int b = gid & (Bq - 1);
    int tgt = gid >> 7;
    float acc = blin[tgt];
    const float* __restrict__ wrow = Wlin + (size_t)tgt * Hq;
#pragma unroll 8
    for (int k = 0; k < Hq; k++) {
        acc += g_hf[k * Bq + b] * wrow[k];
    }
    out[(size_t)b * TGTq + tgt] = acc;
}

// ---------------------------------------------------------------------------
extern "C" void kernel_launch(void* const* d_in, const int* in_sizes, int n_in,
                              void* d_out, int out_size)
{
    const float* XW   = (const float*)d_in[0];
    const float* Wih  = (const float*)d_in[1];
    const float* Whh  = (const float*)d_in[2];
    const float* bih  = (const float*)d_in[3];
    const float* bhh  = (const float*)d_in[4];
    const float* Wlin = (const float*)d_in[5];
    const float* blin = (const float*)d_in[6];
    float* out = (float*)d_out;

    cudaFuncSetAttribute(k_xproj, cudaFuncAttributeMaxDynamicSharedMemorySize, SMEM_XP);
    cudaFuncSetAttribute(k_recur, cudaFuncAttributeMaxDynamicSharedMemorySize, SMEM_PERS);

    k_prep_w<<<G4, 256>>>(Wih, Whh);
    k_prep_x<<<NB, 256>>>(XW);
    k_init<<<128, 256>>>();
    k_xproj<<<dim3(32, 512, 1), 256, SMEM_XP>>>();
    k_recur<<<NCTA, 256, SMEM_PERS>>>(bih, bhh);
    k_lin<<<(Bq * TGTq) / 256, 256>>>(Wlin, blin, out);
}

// round 10
// speedup vs baseline: 6.0357x; 1.2150x over previous
#include <cuda_runtime.h>
#include <cuda_fp16.h>
#include <math.h>
#include <stdint.h>

#define Bq   128
#define Tq   512
#define Iq   512
#define Hq   1024
#define G4   4096
#define TGTq 512
#define NB   65536   // Tq * Bq
#define NCTA 128

// ---------------- persistent-kernel SMEM layout (A-hi resident) ----------
#define PA          1032                   // A row pitch (halves): 1024 + 8 pad
#define A_SPL_B     (32 * PA * 2)          // 66048 B
// request >114KB so at most 1 CTA/SM can be resident (co-residency insurance)
#define SMEM_PERS   (2 * A_SPL_B + 16)     // 132112 B (only first half used)

// ---------------- xproj GEMM SMEM layout ---------------------------------
#define SP          72
#define REG_BYTES   (128 * SP * 2)         // 18432
#define XBUF_BYTES  (3 * REG_BYTES)        // Ah, Al, Bx
#define SMEM_XP     (2 * XBUF_BYTES)       // 110592 B

// ---------------------------------------------------------------------------
// Persistent device scratch (no cudaMalloc allowed)
// ---------------------------------------------------------------------------
__device__ __align__(16) __half g_Wr_h[(size_t)G4 * Hq];   // Whh fp16 (single)
__device__ __align__(16) __half g_Wi_h[(size_t)G4 * Iq];   // Wih hi
__device__ __align__(16) __half g_Wi_l[(size_t)G4 * Iq];   // Wih lo
__device__ __align__(16) __half g_xh[(size_t)NB * Iq];     // x fp16 [t*128+b][i]
// h in mma-B-fragment layout (fp16 single): [buf][(kb*16+bg)*32+lane] = {r0,r1}
__device__ __align__(16) uint2 g_hB[2][64 * 16 * 32];
__device__ float g_hf[Hq * Bq];                            // [u][b] final h
__device__ float g_xp[(size_t)G4 * NB];                    // x-proj [row][t*128+b]
__device__ unsigned g_cnt[8];
__device__ unsigned g_cnt2;
__device__ unsigned g_gen;

// ---------------------------------------------------------------------------
// PTX helpers (plain sm_100 feature set)
// ---------------------------------------------------------------------------
__device__ __forceinline__ uint32_t smem_u32(const void* p) {
    uint32_t a;
    asm("{ .reg .u64 t; cvta.to.shared.u64 t, %1; cvt.u32.u64 %0, t; }"
        : "=r"(a) : "l"(p));
    return a;
}
__device__ __forceinline__ void ldsm4(uint32_t* r, uint32_t addr) {
    asm volatile("ldmatrix.sync.aligned.m8n8.x4.shared.b16 {%0,%1,%2,%3}, [%4];"
                 : "=r"(r[0]), "=r"(r[1]), "=r"(r[2]), "=r"(r[3]) : "r"(addr));
}
__device__ __forceinline__ void ldsm2(uint32_t* r, uint32_t addr) {
    asm volatile("ldmatrix.sync.aligned.m8n8.x2.shared.b16 {%0,%1}, [%2];"
                 : "=r"(r[0]), "=r"(r[1]) : "r"(addr));
}
__device__ __forceinline__ void mma16816(float* c, const uint32_t* a, const uint32_t* b) {
    asm volatile(
        "mma.sync.aligned.m16n8k16.row.col.f32.f16.f16.f32 "
        "{%0,%1,%2,%3}, {%4,%5,%6,%7}, {%8,%9}, {%0,%1,%2,%3};"
        : "+f"(c[0]), "+f"(c[1]), "+f"(c[2]), "+f"(c[3])
        : "r"(a[0]), "r"(a[1]), "r"(a[2]), "r"(a[3]), "r"(b[0]), "r"(b[1]));
}
__device__ __forceinline__ void ldg_cg_v2(uint2& v, const uint2* p) {
    asm volatile("ld.global.cg.v2.u32 {%0,%1}, [%2];"
                 : "=r"(v.x), "=r"(v.y) : "l"(p));
}
#define CP16(d, s) \
    asm volatile("cp.async.cg.shared.global [%0], [%1], 16;" :: "r"(d), "l"(s) : "memory")
#define CPCOMMIT() asm volatile("cp.async.commit_group;" ::: "memory")

__device__ __forceinline__ float sigf(float x) {
    return __fdividef(1.0f, 1.0f + __expf(-x));
}
__device__ __forceinline__ float tanhfast(float x) {
    return __fdividef(2.0f, 1.0f + __expf(-2.0f * x)) - 1.0f;
}

// two-level sense-reversing grid barrier (8 groups of 16 CTAs)
__device__ __forceinline__ void gbar() {
    __syncthreads();
    if (threadIdx.x == 0) {
        unsigned gen;
        asm volatile("ld.acquire.gpu.global.u32 %0, [%1];"
                     : "=r"(gen) : "l"(&g_gen) : "memory");
        __threadfence();
        unsigned grp = blockIdx.x >> 4;
        if (atomicAdd(&g_cnt[grp], 1u) == 15u) {
            atomicExch(&g_cnt[grp], 0u);
            if (atomicAdd(&g_cnt2, 1u) == 7u) {
                atomicExch(&g_cnt2, 0u);
                __threadfence();
                asm volatile("st.release.gpu.global.u32 [%0], %1;"
                             :: "l"(&g_gen), "r"(gen + 1) : "memory");
            }
        }
        unsigned cur;
        do {
            asm volatile("ld.acquire.gpu.global.u32 %0, [%1];"
                         : "=r"(cur) : "l"(&g_gen) : "memory");
            if (cur != gen) break;
            asm volatile("nanosleep.u32 32;");
        } while (1);
    }
    __syncthreads();
}

// ---------------------------------------------------------------------------
// Prep kernels
// ---------------------------------------------------------------------------
__global__ void k_prep_w(const float* __restrict__ Wih, const float* __restrict__ Whh) {
    int r = blockIdx.x;
    for (int k = threadIdx.x; k < Hq; k += 256) {
        g_Wr_h[(size_t)r * Hq + k] = __float2half_rn(Whh[(size_t)r * Hq + k]);
    }
    for (int k = threadIdx.x; k < Iq; k += 256) {
        float w = Wih[(size_t)r * Iq + k];
        __half hi = __float2half_rn(w);
        g_Wi_h[(size_t)r * Iq + k] = hi;
        g_Wi_l[(size_t)r * Iq + k] = __float2half_rn(w - __half2float(hi));
    }
}

__global__ void k_prep_x(const float* __restrict__ XW) {
    int bx = blockIdx.x;          // t*128 + b
    int t = bx >> 7, b = bx & 127;
    const float* __restrict__ src = XW + ((size_t)b * Tq + t) * Iq;
    size_t doff = (size_t)bx * Iq;
    for (int i = threadIdx.x; i < Iq; i += 256) {
        g_xh[doff + i] = __float2half_rn(src[i]);
    }
}

__global__ void k_init() {
    if (blockIdx.x == 0 && threadIdx.x < 8) g_cnt[threadIdx.x] = 0;
    if (blockIdx.x == 0 && threadIdx.x == 8) { g_cnt2 = 0; g_gen = 0; }
    int n = 64 * 16 * 32;
    uint2 z = make_uint2(0, 0);
    for (int i = blockIdx.x * blockDim.x + threadIdx.x; i < n;
         i += gridDim.x * blockDim.x) {
        g_hB[0][i] = z;
        g_hB[1][i] = z;
    }
}

// ---------------------------------------------------------------------------
// x-projection GEMM (fp16 2-term split on W): g_xp = Wih * x^T
// grid (32, 512): C tile 128(M of 4096) x 128(N of 65536), K=512.
// ---------------------------------------------------------------------------
__global__ __launch_bounds__(256) void k_xproj() {
    extern __shared__ __align__(128) uint8_t smem[];
    const uint32_t sb = smem_u32(smem);
    const int tid = threadIdx.x;
    const int L = tid & 31, w = tid >> 5;
    const int mw = w & 3, nw = w >> 2;   // warp tile M32 x N64

    const int mrow0 = blockIdx.x * 128;
    const int nrow0 = blockIdx.y * 128;
    const int lsc = tid & 7;

    const uint32_t a_off = ((mw * 32 + (L & 15)) * SP + (L >> 4) * 8) * 2;
    const uint32_t b_off = ((nw * 64 + (L & 7)) * SP + ((L >> 3) & 1) * 8) * 2;

    float acc[2][8][4];
#pragma unroll
    for (int mi = 0; mi < 2; mi++)
#pragma unroll
        for (int nj = 0; nj < 8; nj++)
#pragma unroll
            for (int q = 0; q < 4; q++) acc[mi][nj][q] = 0.0f;

    auto load_chunk = [&](int buf, int ch) {
        const int gk = ch * 64 + lsc * 8;
        const uint32_t dstbase = sb + buf * XBUF_BYTES;
#pragma unroll
        for (int i = 0; i < 4; i++) {
            int row = (tid >> 3) + i * 32;
            uint32_t doff = (uint32_t)row * 144 + lsc * 16;
            size_t ao = (size_t)(mrow0 + row) * Iq + gk;
            size_t bo = (size_t)(nrow0 + row) * Iq + gk;
            CP16(dstbase + 0 * REG_BYTES + doff, g_Wi_h + ao);
            CP16(dstbase + 1 * REG_BYTES + doff, g_Wi_l + ao);
            CP16(dstbase + 2 * REG_BYTES + doff, g_xh + bo);
        }
        CPCOMMIT();
    };

    load_chunk(0, 0);
    load_chunk(1, 1);
    for (int c = 0; c < 8; c++) {
        if (c < 7) asm volatile("cp.async.wait_group 1;" ::: "memory");
        else       asm volatile("cp.async.wait_group 0;" ::: "memory");
        __syncthreads();
        const uint32_t base = sb + (c & 1) * XBUF_BYTES;
#pragma unroll
        for (int ki = 0; ki < 4; ki++) {
            uint32_t ah[2][4], al[2][4], bh[8][2];
#pragma unroll
            for (int mi = 0; mi < 2; mi++) {
                uint32_t ad = base + a_off + (mi * 16 * SP + ki * 16) * 2;
                ldsm4(ah[mi], ad);
                ldsm4(al[mi], ad + REG_BYTES);
            }
#pragma unroll
            for (int nj = 0; nj < 8; nj++) {
                uint32_t bd = base + 2 * REG_BYTES + b_off + (nj * 8 * SP + ki * 16) * 2;
                ldsm2(bh[nj], bd);
            }
#pragma unroll
            for (int mi = 0; mi < 2; mi++)
#pragma unroll
                for (int nj = 0; nj < 8; nj++) {
                    mma16816(acc[mi][nj], ah[mi], bh[nj]);
                    mma16816(acc[mi][nj], al[mi], bh[nj]);
                }
        }
        if (c + 2 < 8) {
            __syncthreads();
            load_chunk(c & 1, c + 2);
        }
    }

#pragma unroll
    for (int mi = 0; mi < 2; mi++)
#pragma unroll
        for (int nj = 0; nj < 8; nj++) {
            int row = mrow0 + mw * 32 + mi * 16 + (L >> 2);
            int col = nrow0 + nw * 64 + nj * 8 + (L & 3) * 2;
            float* p = g_xp + (size_t)row * NB + col;
            *(float2*)p            = make_float2(acc[mi][nj][0], acc[mi][nj][1]);
            *(float2*)(p + 8 * NB) = make_float2(acc[mi][nj][2], acc[mi][nj][3]);
        }
}

// ---------------------------------------------------------------------------
// Persistent recurrence. CTA c owns hidden units u = c*8..c*8+7 (32 gate rows).
// A = Whh single fp16, resident in SMEM (read once per warp per step);
// B = h (single fp16) read as fragment pairs via ld.cg into a fully unrolled
// register ring. Cell state in regs; next h written in B-fragment layout.
// ---------------------------------------------------------------------------
__global__ __launch_bounds__(256, 1) void k_recur(const float* __restrict__ bih,
                                                  const float* __restrict__ bhh) {
    extern __shared__ __align__(128) uint8_t smem[];
    const uint32_t sb = smem_u32(smem);
    const int tid = threadIdx.x;
    const int c = blockIdx.x;
    const int L = tid & 31;
    const int nw = tid >> 5;             // warp = N group of 16 batch cols

    // ---- load resident A (Whh fp16) : 32 rows x 1024 halves ----
    {
        int row32 = tid >> 3;            // 0..31
        int g = row32 >> 3, j = row32 & 7;
        size_t grow = ((size_t)g * Hq + c * 8 + j) * Hq;
        int seg = tid & 7;
#pragma unroll
        for (int it = 0; it < 16; it++) {
            int s16 = seg + it * 8;
            uint32_t doff = (uint32_t)row32 * (PA * 2) + s16 * 16;
            CP16(sb + doff, g_Wr_h + grow + s16 * 8);
        }
        CPCOMMIT();
    }

    // per-thread cell mapping
    const int j = (L >> 2) & 7;          // unit within CTA
    const int u = c * 8 + j;             // global hidden unit
    const int c0 = nw * 16 + (L & 3) * 2; // batch cols c0,c0+1,c0+8,c0+9
    float bias[4], cc[4];
#pragma unroll
    for (int g = 0; g < 4; g++) {
        bias[g] = bih[g * Hq + u] + bhh[g * Hq + u];
        cc[g] = 0.0f;                    // cc indexed by (nj*2+e)
    }

    // producer store mapping for h fragments
    const int p_kb   = u >> 4;
    const int p_ln   = ((u >> 1) & 3);
    const int p_boff = ((u >> 3) & 1) * 4 + (u & 1) * 2;

    const uint32_t aoff = (((L & 15) * PA + (L >> 4) * 8)) * 2;
    const int bgBase = nw * 2;

    asm volatile("cp.async.wait_group 0;" ::: "memory");
    __syncthreads();

    // xp prefetch for first step
    float2 xpv[4][2];
#pragma unroll
    for (int g = 0; g < 4; g++)
#pragma unroll
        for (int nj = 0; nj < 2; nj++)
            xpv[g][nj] = *(const float2*)&g_xp[(size_t)(g * Hq + u) * NB
                                               + (Tq - 1) * Bq + c0 + nj * 8];

    for (int s = 0; s < Tq; s++) {
        const uint2* __restrict__ hBin = g_hB[s & 1];
        uint2* __restrict__ hBout      = g_hB[(s + 1) & 1];

        float acc[2][2][4];
#pragma unroll
        for (int mi = 0; mi < 2; mi++)
#pragma unroll
            for (int nj = 0; nj < 2; nj++)
#pragma unroll
                for (int q = 0; q < 4; q++) acc[mi][nj][q] = 0.0f;

        uint2 Bp[4][8];   // 4-slot ring, compile-time indices only

#define LOADB(G, SLOT)                                                        \
        {                                                                     \
            _Pragma("unroll")                                                 \
            for (int kk = 0; kk < 4; kk++)                                    \
                _Pragma("unroll")                                             \
                for (int nj = 0; nj < 2; nj++)                                \
                    ldg_cg_v2(Bp[SLOT][kk * 2 + nj],                          \
                              hBin + (((G) * 4 + kk) * 16 + bgBase + nj) * 32 + L); \
        }

        LOADB(0, 0); LOADB(1, 1); LOADB(2, 2);

#pragma unroll
        for (int g = 0; g < 16; g++) {
            if (g + 3 < 16) {
                const int ng = g + 3;
                const int ns = ng & 3;
                LOADB(ng, ns);
            }
            const int slot = g & 3;
#pragma unroll
            for (int kk = 0; kk < 4; kk++) {
                const int k = (g * 4 + kk) * 16;
                uint32_t ah[2][4];
#pragma unroll
                for (int mi = 0; mi < 2; mi++) {
                    uint32_t ad = sb + aoff + (uint32_t)(mi * 16 * PA + k) * 2;
                    ldsm4(ah[mi], ad);
                }
#pragma unroll
                for (int nj = 0; nj < 2; nj++) {
                    uint32_t bh[2] = { Bp[slot][kk * 2 + nj].x, Bp[slot][kk * 2 + nj].y };
#pragma unroll
                    for (int mi = 0; mi < 2; mi++) {
                        mma16816(acc[mi][nj], ah[mi], bh);
                    }
                }
            }
        }
#undef LOADB

        // ---- register-local cell update for 4 (batch) positions ----
        const bool last = (s == Tq - 1);
#pragma unroll
        for (int nj = 0; nj < 2; nj++)
#pragma unroll
            for (int e = 0; e < 2; e++) {
                int b = c0 + nj * 8 + e;
                float xpi = e ? xpv[0][nj].y : xpv[0][nj].x;
                float xpf = e ? xpv[1][nj].y : xpv[1][nj].x;
                float xpg = e ? xpv[2][nj].y : xpv[2][nj].x;
                float xpo = e ? xpv[3][nj].y : xpv[3][nj].x;
                float ig = sigf(acc[0][nj][e]     + xpi + bias[0]);
                float fg = sigf(acc[0][nj][2 + e] + xpf + bias[1]);
                float gg = tanhfast(acc[1][nj][e]    + xpg + bias[2]);
                float og = sigf(acc[1][nj][2 + e] + xpo + bias[3]);
                int ci = nj * 2 + e;
                float cv = fg * cc[ci] + ig * gg;
                cc[ci] = cv;
                float h = og * tanhfast(cv);
                int lane = ((b & 7) << 2) | p_ln;
                char* qp = (char*)&hBout[(p_kb * 16 + (b >> 3)) * 32 + lane];
                *(__half*)(qp + p_boff) = __float2half_rn(h);
                if (last) g_hf[u * Bq + b] = h;
            }

        // prefetch next step's xp before the barrier (read-only, precomputed)
        if (!last) {
            const int tn = Tq - 2 - s;
#pragma unroll
            for (int g = 0; g < 4; g++)
#pragma unroll
                for (int nj = 0; nj < 2; nj++)
                    xpv[g][nj] = *(const float2*)&g_xp[(size_t)(g * Hq + u) * NB
                                                       + tn * Bq + c0 + nj * 8];
            gbar();
        }
    }
}

// ---------------------------------------------------------------------------
// Final linear
// ---------------------------------------------------------------------------
__global__ __launch_bounds__(256) void k_lin(const float* __restrict__ Wlin,
                                             const float* __restrict__ blin,
                                             float* __restrict__ out) {
    int gid = blockIdx.x * blockDim.x + threadIdx.x;
    int b = gid & (Bq - 1);
    int tgt = gid >> 7;
    float acc = blin[tgt];
    const float* __restrict__ wrow = Wlin + (size_t)tgt * Hq;
#pragma unroll 8
    for (int k = 0; k < Hq; k++) {
        acc += g_hf[k * Bq + b] * wrow[k];
    }
    out[(size_t)b * TGTq + tgt] = acc;
}

// ---------------------------------------------------------------------------
extern "C" void kernel_launch(void* const* d_in, const int* in_sizes, int n_in,
                              void* d_out, int out_size)
{
    const float* XW   = (const float*)d_in[0];
    const float* Wih  = (const float*)d_in[1];
    const float* Whh  = (const float*)d_in[2];
    const float* bih  = (const float*)d_in[3];
    const float* bhh  = (const float*)d_in[4];
    const float* Wlin = (const float*)d_in[5];
    const float* blin = (const float*)d_in[6];
    float* out = (float*)d_out;

    cudaFuncSetAttribute(k_xproj, cudaFuncAttributeMaxDynamicSharedMemorySize, SMEM_XP);
    cudaFuncSetAttribute(k_recur, cudaFuncAttributeMaxDynamicSharedMemorySize, SMEM_PERS);

    k_prep_w<<<G4, 256>>>(Wih, Whh);
    k_prep_x<<<NB, 256>>>(XW);
    k_init<<<128, 256>>>();
    k_xproj<<<dim3(32, 512, 1), 256, SMEM_XP>>>();
    k_recur<<<NCTA, 256, SMEM_PERS>>>(bih, bhh);
    k_lin<<<(Bq * TGTq) / 256, 256>>>(Wlin, blin, out);
}